// round 1
// baseline (speedup 1.0000x reference)
#include <cuda_runtime.h>
#include <math.h>

#define S_LEN  2048
#define B_SZ   2
#define H_DIM  4096
#define NHEADS 32
#define NGRP   2
#define HDIM   128
#define O_QKV  4608          // NH*HD + 2*NG*HD
#define M_ROWS 4096          // S*B

// Scratch (allocation-free rule: __device__ globals)
__device__ float g_mixed[M_ROWS * O_QKV];   // ~75.5 MB
__device__ float g_ctx[M_ROWS * H_DIM];     // 64 MB

// ---------------------------------------------------------------------------
// GEMM: C[M,N] = A[M,K] @ W[N,K]^T (+ bias[N]).  128x128x16 tile, 8x8/thread.
// ---------------------------------------------------------------------------
__global__ __launch_bounds__(256) void gemm_bias_kernel(
    const float* __restrict__ A, const float* __restrict__ W,
    const float* __restrict__ bias, float* __restrict__ C,
    int M, int N, int K)
{
    __shared__ float As[16][128];
    __shared__ float Ws[16][128];

    const int tid = threadIdx.x;
    const int ty  = tid >> 4;      // 0..15
    const int tx  = tid & 15;      // 0..15
    const int row0 = blockIdx.y * 128;
    const int col0 = blockIdx.x * 128;

    float acc[8][8];
#pragma unroll
    for (int i = 0; i < 8; i++)
#pragma unroll
        for (int j = 0; j < 8; j++) acc[i][j] = 0.f;

    for (int kt = 0; kt < K; kt += 16) {
#pragma unroll
        for (int u = 0; u < 2; u++) {
            int idx = tid + u * 256;         // 0..511
            int r   = idx >> 2;              // 0..127
            int c4  = (idx & 3) << 2;        // 0,4,8,12
            float4 va = *(const float4*)&A[(size_t)(row0 + r) * K + kt + c4];
            As[c4 + 0][r] = va.x; As[c4 + 1][r] = va.y;
            As[c4 + 2][r] = va.z; As[c4 + 3][r] = va.w;
            float4 vw = *(const float4*)&W[(size_t)(col0 + r) * K + kt + c4];
            Ws[c4 + 0][r] = vw.x; Ws[c4 + 1][r] = vw.y;
            Ws[c4 + 2][r] = vw.z; Ws[c4 + 3][r] = vw.w;
        }
        __syncthreads();

#pragma unroll
        for (int k = 0; k < 16; k++) {
            float a[8], b[8];
            *(float4*)&a[0] = *(const float4*)&As[k][ty * 8];
            *(float4*)&a[4] = *(const float4*)&As[k][ty * 8 + 4];
            *(float4*)&b[0] = *(const float4*)&Ws[k][tx * 8];
            *(float4*)&b[4] = *(const float4*)&Ws[k][tx * 8 + 4];
#pragma unroll
            for (int i = 0; i < 8; i++)
#pragma unroll
                for (int j = 0; j < 8; j++) acc[i][j] += a[i] * b[j];
        }
        __syncthreads();
    }

#pragma unroll
    for (int i = 0; i < 8; i++) {
        size_t row = (size_t)(row0 + ty * 8 + i);
        int col = col0 + tx * 8;
        float o[8];
#pragma unroll
        for (int j = 0; j < 8; j++)
            o[j] = acc[i][j] + (bias ? bias[col + j] : 0.f);
        *(float4*)&C[row * N + col]     = *(float4*)&o[0];
        *(float4*)&C[row * N + col + 4] = *(float4*)&o[4];
    }
}

// ---------------------------------------------------------------------------
// RoPE in-place on g_mixed: Q heads (0..31) + K heads (2), first 64 dims.
// ---------------------------------------------------------------------------
__global__ __launch_bounds__(256) void rope_kernel(const float* __restrict__ rope)
{
    int idx = blockIdx.x * blockDim.x + threadIdx.x;
    const int TOTAL = S_LEN * B_SZ * (NHEADS + NGRP) * 32;
    if (idx >= TOTAL) return;
    int i  = idx & 31;               // pair index 0..31
    int t  = idx >> 5;
    int hh = t % (NHEADS + NGRP);    // 0..33
    int sb = t / (NHEADS + NGRP);    // row index s*2+b
    int s  = sb >> 1;

    size_t row = (size_t)sb * O_QKV;
    int off = (hh < NHEADS) ? hh * HDIM : (NHEADS * HDIM + (hh - NHEADS) * HDIM);

    float c  = rope[s * 64 + 2 * i];
    float sn = rope[s * 64 + 2 * i + 1];
    float x0 = g_mixed[row + off + 2 * i];
    float x1 = g_mixed[row + off + 2 * i + 1];
    g_mixed[row + off + 2 * i]     = x0 * c - x1 * sn;
    g_mixed[row + off + 2 * i + 1] = x1 * c + x0 * sn;
}

// ---------------------------------------------------------------------------
// Flash attention (causal, GQA). BQ=BK=64, 256 threads.
// smem: Qst [128][72] transposed, KV buffer (Kst [128][72] then V [64][128]),
//       Ps [64][65].  Online softmax kept in registers (width-16 shuffles).
// ---------------------------------------------------------------------------
#define SM_QST 0
#define SM_KV  9216          // 128*72
#define SM_PS  18432         // + 128*72
#define SM_FLOATS 22592      // + 64*65

__global__ __launch_bounds__(256) void flash_kernel()
{
    extern __shared__ float sm[];
    float* Qst = sm + SM_QST;
    float* KV  = sm + SM_KV;
    float* Ps  = sm + SM_PS;

    const int qb = blockIdx.x;     // 0..31
    const int h  = blockIdx.y;     // 0..31
    const int b  = blockIdx.z;     // 0..1
    const int g  = h >> 4;         // group (r = 16)
    const int tid = threadIdx.x;
    const int ty = tid >> 4, tx = tid & 15;
    const float scale = 0.08838834764831843f;   // 1/sqrt(128)

    // Load Q tile transposed (pre-scaled): Qst[d][qr]
    for (int idx = tid; idx < 2048; idx += 256) {
        int r  = idx >> 5;
        int c4 = (idx & 31) << 2;
        const float4 v = *(const float4*)
            &g_mixed[((size_t)((qb * 64 + r) * 2 + b)) * O_QKV + h * HDIM + c4];
        Qst[(c4 + 0) * 72 + r] = v.x * scale;
        Qst[(c4 + 1) * 72 + r] = v.y * scale;
        Qst[(c4 + 2) * 72 + r] = v.z * scale;
        Qst[(c4 + 3) * 72 + r] = v.w * scale;
    }

    float m_i[4], l_i[4], o[4][8];
#pragma unroll
    for (int i = 0; i < 4; i++) {
        m_i[i] = -INFINITY; l_i[i] = 0.f;
#pragma unroll
        for (int j = 0; j < 8; j++) o[i][j] = 0.f;
    }

    for (int kb = 0; kb <= qb; kb++) {
        __syncthreads();   // covers Q-load (iter 0) + KV buffer reuse
        // Load K transposed: KV[d][kr]
        for (int idx = tid; idx < 2048; idx += 256) {
            int r  = idx >> 5;
            int c4 = (idx & 31) << 2;
            const float4 v = *(const float4*)
                &g_mixed[((size_t)((kb * 64 + r) * 2 + b)) * O_QKV + 4096 + g * HDIM + c4];
            KV[(c4 + 0) * 72 + r] = v.x;
            KV[(c4 + 1) * 72 + r] = v.y;
            KV[(c4 + 2) * 72 + r] = v.z;
            KV[(c4 + 3) * 72 + r] = v.w;
        }
        __syncthreads();

        // S tile: 4x4 per thread, rows ty*4+i, cols tx*4+j
        float acc[4][4];
#pragma unroll
        for (int i = 0; i < 4; i++)
#pragma unroll
            for (int j = 0; j < 4; j++) acc[i][j] = 0.f;

        for (int d = 0; d < 128; d++) {
            float4 q = *(const float4*)&Qst[d * 72 + ty * 4];
            float4 k = *(const float4*)&KV[d * 72 + tx * 4];
            acc[0][0] += q.x * k.x; acc[0][1] += q.x * k.y; acc[0][2] += q.x * k.z; acc[0][3] += q.x * k.w;
            acc[1][0] += q.y * k.x; acc[1][1] += q.y * k.y; acc[1][2] += q.y * k.z; acc[1][3] += q.y * k.w;
            acc[2][0] += q.z * k.x; acc[2][1] += q.z * k.y; acc[2][2] += q.z * k.z; acc[2][3] += q.z * k.w;
            acc[3][0] += q.w * k.x; acc[3][1] += q.w * k.y; acc[3][2] += q.w * k.z; acc[3][3] += q.w * k.w;
        }

        if (kb == qb) {   // diagonal block: causal mask
#pragma unroll
            for (int i = 0; i < 4; i++)
#pragma unroll
                for (int j = 0; j < 4; j++)
                    if (tx * 4 + j > ty * 4 + i) acc[i][j] = -1e30f;
        }

        float escale[4];
#pragma unroll
        for (int i = 0; i < 4; i++) {
            float rm = fmaxf(fmaxf(acc[i][0], acc[i][1]), fmaxf(acc[i][2], acc[i][3]));
#pragma unroll
            for (int w = 8; w; w >>= 1)
                rm = fmaxf(rm, __shfl_xor_sync(0xffffffffu, rm, w, 16));
            float mnew = fmaxf(m_i[i], rm);
            escale[i] = __expf(m_i[i] - mnew);
            float rs = 0.f;
#pragma unroll
            for (int j = 0; j < 4; j++) {
                float p = __expf(acc[i][j] - mnew);
                acc[i][j] = p;
                rs += p;
            }
#pragma unroll
            for (int w = 8; w; w >>= 1)
                rs += __shfl_xor_sync(0xffffffffu, rs, w, 16);
            m_i[i] = mnew;
            l_i[i] = l_i[i] * escale[i] + rs;
            Ps[(ty * 4 + i) * 65 + tx * 4 + 0] = acc[i][0];
            Ps[(ty * 4 + i) * 65 + tx * 4 + 1] = acc[i][1];
            Ps[(ty * 4 + i) * 65 + tx * 4 + 2] = acc[i][2];
            Ps[(ty * 4 + i) * 65 + tx * 4 + 3] = acc[i][3];
        }
        __syncthreads();  // Ps written; Kst no longer needed

        // Load V into KV as [t][128]
        for (int idx = tid; idx < 2048; idx += 256) {
            int r  = idx >> 5;
            int c4 = (idx & 31) << 2;
            const float4 v = *(const float4*)
                &g_mixed[((size_t)((kb * 64 + r) * 2 + b)) * O_QKV + 4352 + g * HDIM + c4];
            *(float4*)&KV[r * 128 + c4] = v;
        }
        __syncthreads();

        // O update: rows ty*4+i, dims tx*8+j
#pragma unroll
        for (int i = 0; i < 4; i++) {
            float e = escale[i];
#pragma unroll
            for (int j = 0; j < 8; j++) o[i][j] *= e;
        }
        for (int t = 0; t < 64; t++) {
            float4 v0 = *(const float4*)&KV[t * 128 + tx * 8];
            float4 v1 = *(const float4*)&KV[t * 128 + tx * 8 + 4];
#pragma unroll
            for (int i = 0; i < 4; i++) {
                float p = Ps[(ty * 4 + i) * 65 + t];
                o[i][0] += p * v0.x; o[i][1] += p * v0.y;
                o[i][2] += p * v0.z; o[i][3] += p * v0.w;
                o[i][4] += p * v1.x; o[i][5] += p * v1.y;
                o[i][6] += p * v1.z; o[i][7] += p * v1.w;
            }
        }
    }

    // Normalize + write ctx[s,b, h*128 + d]
#pragma unroll
    for (int i = 0; i < 4; i++) {
        float inv = 1.f / l_i[i];
        size_t base = ((size_t)((qb * 64 + ty * 4 + i) * 2 + b)) * H_DIM + h * HDIM + tx * 8;
        float r0[4] = { o[i][0] * inv, o[i][1] * inv, o[i][2] * inv, o[i][3] * inv };
        float r1[4] = { o[i][4] * inv, o[i][5] * inv, o[i][6] * inv, o[i][7] * inv };
        *(float4*)&g_ctx[base]     = *(float4*)&r0[0];
        *(float4*)&g_ctx[base + 4] = *(float4*)&r1[0];
    }
}

// ---------------------------------------------------------------------------
extern "C" void kernel_launch(void* const* d_in, const int* in_sizes, int n_in,
                              void* d_out, int out_size)
{
    const float* hidden = (const float*)d_in[0];
    // d_in[1] = attention_mask (causal, hardcoded) — unused
    const float* rope   = (const float*)d_in[2];
    const float* Wqkv   = (const float*)d_in[3];
    const float* bqkv   = (const float*)d_in[4];
    const float* Wd     = (const float*)d_in[5];
    float* out = (float*)d_out;

    float *mixed, *ctx;
    cudaGetSymbolAddress((void**)&mixed, g_mixed);
    cudaGetSymbolAddress((void**)&ctx,   g_ctx);

    // 1) QKV projection + bias
    dim3 g1(O_QKV / 128, M_ROWS / 128);
    gemm_bias_kernel<<<g1, 256>>>(hidden, Wqkv, bqkv, mixed, M_ROWS, O_QKV, H_DIM);

    // 2) RoPE in place
    const int total = S_LEN * B_SZ * (NHEADS + NGRP) * 32;
    rope_kernel<<<(total + 255) / 256, 256>>>(rope);

    // 3) Flash attention
    cudaFuncSetAttribute(flash_kernel,
                         cudaFuncAttributeMaxDynamicSharedMemorySize,
                         SM_FLOATS * 4);
    flash_kernel<<<dim3(S_LEN / 64, NHEADS, B_SZ), 256, SM_FLOATS * 4>>>();

    // 4) Dense projection
    dim3 g2(H_DIM / 128, M_ROWS / 128);
    gemm_bias_kernel<<<g2, 256>>>(ctx, Wd, nullptr, out, M_ROWS, H_DIM, H_DIM);
}

// round 4
// speedup vs baseline: 1.9442x; 1.9442x over previous
#include <cuda_runtime.h>
#include <math.h>
#include <stdint.h>

#define S_LEN  2048
#define B_SZ   2
#define H_DIM  4096
#define NHEADS 32
#define NGRP   2
#define HDIM   128
#define O_QKV  4608
#define M_ROWS 4096

// ---------------- scratch (__device__ globals; allocation-free rule) --------
__device__ float g_mixed[M_ROWS * O_QKV];
__device__ float g_ctx[M_ROWS * H_DIM];
__device__ float g_hid[M_ROWS * H_DIM];
__device__ float g_wq[O_QKV * H_DIM];
__device__ float g_wd[H_DIM * H_DIM];

// ---------------- helpers ----------------------------------------------------
__device__ __forceinline__ uint32_t smem_u32(const void* p) {
    uint32_t a;
    asm("{ .reg .u64 t; cvta.to.shared.u64 t, %1; cvt.u32.u64 %0, t; }" : "=r"(a) : "l"(p));
    return a;
}
__device__ __forceinline__ float rna_tf32(float x) {
    float r; asm("cvt.rna.tf32.f32 %0, %1;" : "=f"(r) : "f"(x)); return r;
}
__device__ __forceinline__ void cp_async16(uint32_t dst, const void* src) {
    asm volatile("cp.async.cg.shared.global [%0], [%1], 16;" :: "r"(dst), "l"(src));
}
__device__ __forceinline__ void cp_commit() {
    asm volatile("cp.async.commit_group;" ::: "memory");
}
template<int N> __device__ __forceinline__ void cp_wait() {
    asm volatile("cp.async.wait_group %0;" :: "n"(N) : "memory");
}
// D += A*B, m16n8k8 tf32
__device__ __forceinline__ void mma8(float* d, const uint32_t* a, const uint32_t* b) {
    asm volatile("mma.sync.aligned.m16n8k8.row.col.f32.tf32.tf32.f32 "
        "{%0,%1,%2,%3}, {%4,%5,%6,%7}, {%8,%9}, {%0,%1,%2,%3};"
        : "+f"(d[0]), "+f"(d[1]), "+f"(d[2]), "+f"(d[3])
        : "r"(a[0]), "r"(a[1]), "r"(a[2]), "r"(a[3]), "r"(b[0]), "r"(b[1]));
}
__device__ __forceinline__ uint32_t f2u(float x) { return __float_as_uint(x); }

// ---------------- tf32 rounding pass ----------------------------------------
__global__ __launch_bounds__(256) void round_tf32_kernel(
    const float4* __restrict__ in, float4* __restrict__ out, int n4)
{
    int i = blockIdx.x * blockDim.x + threadIdx.x;
    if (i >= n4) return;
    float4 v = in[i];
    v.x = rna_tf32(v.x); v.y = rna_tf32(v.y);
    v.z = rna_tf32(v.z); v.w = rna_tf32(v.w);
    out[i] = v;
}

// ---------------- mma.sync tf32 GEMM: C[M,N] = A[M,K] @ W[N,K]^T (+bias) ----
// CTA 128x128, 256 thr (warp grid 2x4, warp tile 64x32), K-chunk 32,
// double-buffered cp.async.  smem stride 36 floats -> conflict-free frags.
#define GS 36
#define GBUF (128 * GS)                 // floats per tile buffer
#define GEMM_SMEM (4 * GBUF * 4)        // A0,A1,B0,B1 = 73728 B

__global__ __launch_bounds__(256) void gemm_mma_kernel(
    const float* __restrict__ A, const float* __restrict__ W,
    const float* __restrict__ bias, float* __restrict__ C,
    int N, int K)
{
    extern __shared__ float sm[];
    float* Asm = sm;                    // 2 buffers
    float* Bsm = sm + 2 * GBUF;
    const uint32_t sA = smem_u32(Asm);
    const uint32_t sB = smem_u32(Bsm);

    const int tid = threadIdx.x;
    const int wid = tid >> 5, lid = tid & 31;
    const int g = lid >> 2, c = lid & 3;
    const int warp_m = wid & 1, warp_n = wid >> 1;
    const int m0 = warp_m * 64, n0 = warp_n * 32;
    const int row0 = blockIdx.y * 128;
    const int col0 = blockIdx.x * 128;

    float acc[4][4][4];
#pragma unroll
    for (int i = 0; i < 4; i++)
#pragma unroll
        for (int j = 0; j < 4; j++)
#pragma unroll
            for (int k = 0; k < 4; k++) acc[i][j][k] = 0.f;

    const int nchunk = K / 32;
    const int lrow = tid >> 1;               // 0..127 (2 threads per row)
    const int lf   = (tid & 1) * 16;         // float offset in row: 0 or 16

    // Each thread: 4 x 16B per operand -> 2 threads cover the full 128B row.
#define LOADCH(ch, bf) do {                                                   \
        const float* _a = A + (size_t)(row0 + lrow) * K + (ch) * 32 + lf;     \
        const float* _b = W + (size_t)(col0 + lrow) * K + (ch) * 32 + lf;     \
        uint32_t _da = sA + (bf) * GBUF * 4 + lrow * 144 + lf * 4;            \
        uint32_t _db = sB + (bf) * GBUF * 4 + lrow * 144 + lf * 4;            \
        cp_async16(_da,      _a);                                             \
        cp_async16(_da + 16, _a + 4);                                         \
        cp_async16(_da + 32, _a + 8);                                         \
        cp_async16(_da + 48, _a + 12);                                        \
        cp_async16(_db,      _b);                                             \
        cp_async16(_db + 16, _b + 4);                                         \
        cp_async16(_db + 32, _b + 8);                                         \
        cp_async16(_db + 48, _b + 12);                                        \
        cp_commit();                                                          \
    } while (0)

    LOADCH(0, 0);

    for (int i = 0; i < nchunk; i++) {
        if (i + 1 < nchunk) { LOADCH(i + 1, (i + 1) & 1); cp_wait<1>(); }
        else cp_wait<0>();
        __syncthreads();

        const float* as = Asm + (i & 1) * GBUF;
        const float* bs = Bsm + (i & 1) * GBUF;
#pragma unroll
        for (int kk = 0; kk < 4; kk++) {
            const int k8 = kk * 8;
            uint32_t af[4][4], bf[4][2];
#pragma unroll
            for (int mt = 0; mt < 4; mt++) {
                const int r = m0 + mt * 16 + g;
                af[mt][0] = f2u(as[r * GS + k8 + c]);
                af[mt][1] = f2u(as[(r + 8) * GS + k8 + c]);
                af[mt][2] = f2u(as[r * GS + k8 + c + 4]);
                af[mt][3] = f2u(as[(r + 8) * GS + k8 + c + 4]);
            }
#pragma unroll
            for (int nt = 0; nt < 4; nt++) {
                const int cl = n0 + nt * 8 + g;
                bf[nt][0] = f2u(bs[cl * GS + k8 + c]);
                bf[nt][1] = f2u(bs[cl * GS + k8 + c + 4]);
            }
#pragma unroll
            for (int mt = 0; mt < 4; mt++)
#pragma unroll
                for (int nt = 0; nt < 4; nt++)
                    mma8(acc[mt][nt], af[mt], bf[nt]);
        }
        __syncthreads();
    }
#undef LOADCH

    // epilogue
#pragma unroll
    for (int mt = 0; mt < 4; mt++) {
#pragma unroll
        for (int nt = 0; nt < 4; nt++) {
            const int rr = row0 + m0 + mt * 16 + g;
            const int cc = col0 + n0 + nt * 8 + 2 * c;
            float b0 = bias ? bias[cc] : 0.f;
            float b1 = bias ? bias[cc + 1] : 0.f;
            float2 v0 = make_float2(acc[mt][nt][0] + b0, acc[mt][nt][1] + b1);
            float2 v1 = make_float2(acc[mt][nt][2] + b0, acc[mt][nt][3] + b1);
            *(float2*)&C[(size_t)rr * N + cc]       = v0;
            *(float2*)&C[(size_t)(rr + 8) * N + cc] = v1;
        }
    }
}

// ---------------- RoPE in place on g_mixed ----------------------------------
__global__ __launch_bounds__(256) void rope_kernel(const float* __restrict__ rope)
{
    int idx = blockIdx.x * blockDim.x + threadIdx.x;
    const int TOTAL = S_LEN * B_SZ * (NHEADS + NGRP) * 32;
    if (idx >= TOTAL) return;
    int i  = idx & 31;
    int t  = idx >> 5;
    int hh = t % (NHEADS + NGRP);
    int sb = t / (NHEADS + NGRP);
    int s  = sb >> 1;

    size_t row = (size_t)sb * O_QKV;
    int off = (hh < NHEADS) ? hh * HDIM : (NHEADS * HDIM + (hh - NHEADS) * HDIM);

    float cc = rope[s * 64 + 2 * i];
    float sn = rope[s * 64 + 2 * i + 1];
    float x0 = g_mixed[row + off + 2 * i];
    float x1 = g_mixed[row + off + 2 * i + 1];
    g_mixed[row + off + 2 * i]     = x0 * cc - x1 * sn;
    g_mixed[row + off + 2 * i + 1] = x1 * cc + x0 * sn;
}

// ---------------- flash attention with mma.sync (tf32) ----------------------
// 128 thr / 4 warps; warp w owns Q rows [w*16, w*16+16) x full 64-col S tile.
// smem: Qs[64][132], KV buffer (K stride 132 / V stride 136), Ps[64][68].
#define FQ_STRIDE 132
#define FV_STRIDE 136
#define FP_STRIDE 68
#define F_QOFF 0
#define F_KVOFF 8448          // 64*132
#define F_POFF  17152         // + 64*136 = 8704
#define FLASH_SMEM ((17152 + 64 * FP_STRIDE) * 4)   // 86016 B

__global__ __launch_bounds__(128) void flash_mma_kernel()
{
    extern __shared__ float sm[];
    float* Qs = sm + F_QOFF;
    float* KVs = sm + F_KVOFF;
    float* Ps = sm + F_POFF;

    const int qb = blockIdx.x, h = blockIdx.y, b = blockIdx.z;
    const int grp = h >> 4;
    const int tid = threadIdx.x, wid = tid >> 5, lid = tid & 31;
    const int g = lid >> 2, c = lid & 3;
    const int m0 = wid * 16;
    const float scale = 0.08838834764831843f;

    // Q tile (scaled + tf32-rounded)
#pragma unroll
    for (int it = 0; it < 16; it++) {
        int idx = tid + it * 128;
        int r = idx >> 5, sg = (idx & 31) << 2;
        float4 v = *(const float4*)
            &g_mixed[((size_t)((qb * 64 + r) * 2 + b)) * O_QKV + h * HDIM + sg];
        float* d = &Qs[r * FQ_STRIDE + sg];
        d[0] = rna_tf32(v.x * scale); d[1] = rna_tf32(v.y * scale);
        d[2] = rna_tf32(v.z * scale); d[3] = rna_tf32(v.w * scale);
    }

    float o[16][4];
#pragma unroll
    for (int nt = 0; nt < 16; nt++)
#pragma unroll
        for (int j = 0; j < 4; j++) o[nt][j] = 0.f;
    float mst0 = -INFINITY, mst1 = -INFINITY, lst0 = 0.f, lst1 = 0.f;

    for (int kb = 0; kb <= qb; kb++) {
        __syncthreads();
        // K tile (tf32-rounded), stride 132
#pragma unroll
        for (int it = 0; it < 16; it++) {
            int idx = tid + it * 128;
            int r = idx >> 5, sg = (idx & 31) << 2;
            float4 v = *(const float4*)
                &g_mixed[((size_t)((kb * 64 + r) * 2 + b)) * O_QKV + 4096 + grp * HDIM + sg];
            float* d = &KVs[r * FQ_STRIDE + sg];
            d[0] = rna_tf32(v.x); d[1] = rna_tf32(v.y);
            d[2] = rna_tf32(v.z); d[3] = rna_tf32(v.w);
        }
        __syncthreads();

        // S = Q @ K^T  (warp: 16 rows x 64 cols -> 8 n-tiles)
        float s[8][4];
#pragma unroll
        for (int nt = 0; nt < 8; nt++)
#pragma unroll
            for (int j = 0; j < 4; j++) s[nt][j] = 0.f;

#pragma unroll
        for (int kk = 0; kk < 16; kk++) {
            const int k8 = kk * 8;
            uint32_t a[4];
            a[0] = f2u(Qs[(m0 + g) * FQ_STRIDE + k8 + c]);
            a[1] = f2u(Qs[(m0 + g + 8) * FQ_STRIDE + k8 + c]);
            a[2] = f2u(Qs[(m0 + g) * FQ_STRIDE + k8 + c + 4]);
            a[3] = f2u(Qs[(m0 + g + 8) * FQ_STRIDE + k8 + c + 4]);
#pragma unroll
            for (int nt = 0; nt < 8; nt++) {
                uint32_t bfr[2];
                bfr[0] = f2u(KVs[(nt * 8 + g) * FQ_STRIDE + k8 + c]);
                bfr[1] = f2u(KVs[(nt * 8 + g) * FQ_STRIDE + k8 + c + 4]);
                mma8(s[nt], a, bfr);
            }
        }

        if (kb == qb) {            // causal mask on diagonal block
            const int r0 = m0 + g, r1 = r0 + 8;
#pragma unroll
            for (int nt = 0; nt < 8; nt++) {
                const int n = nt * 8 + 2 * c;
                if (n > r0)     s[nt][0] = -1e30f;
                if (n + 1 > r0) s[nt][1] = -1e30f;
                if (n > r1)     s[nt][2] = -1e30f;
                if (n + 1 > r1) s[nt][3] = -1e30f;
            }
        }

        // online softmax (rows g and g+8; full row lives in the 4-lane group)
        float rm0 = -INFINITY, rm1 = -INFINITY;
#pragma unroll
        for (int nt = 0; nt < 8; nt++) {
            rm0 = fmaxf(rm0, fmaxf(s[nt][0], s[nt][1]));
            rm1 = fmaxf(rm1, fmaxf(s[nt][2], s[nt][3]));
        }
        rm0 = fmaxf(rm0, __shfl_xor_sync(0xffffffffu, rm0, 1));
        rm0 = fmaxf(rm0, __shfl_xor_sync(0xffffffffu, rm0, 2));
        rm1 = fmaxf(rm1, __shfl_xor_sync(0xffffffffu, rm1, 1));
        rm1 = fmaxf(rm1, __shfl_xor_sync(0xffffffffu, rm1, 2));
        const float mn0 = fmaxf(mst0, rm0);
        const float mn1 = fmaxf(mst1, rm1);
        const float es0 = __expf(mst0 - mn0);
        const float es1 = __expf(mst1 - mn1);
        float rs0 = 0.f, rs1 = 0.f;
#pragma unroll
        for (int nt = 0; nt < 8; nt++) {
            s[nt][0] = __expf(s[nt][0] - mn0);
            s[nt][1] = __expf(s[nt][1] - mn0);
            s[nt][2] = __expf(s[nt][2] - mn1);
            s[nt][3] = __expf(s[nt][3] - mn1);
            rs0 += s[nt][0] + s[nt][1];
            rs1 += s[nt][2] + s[nt][3];
        }
        rs0 += __shfl_xor_sync(0xffffffffu, rs0, 1);
        rs0 += __shfl_xor_sync(0xffffffffu, rs0, 2);
        rs1 += __shfl_xor_sync(0xffffffffu, rs1, 1);
        rs1 += __shfl_xor_sync(0xffffffffu, rs1, 2);
        mst0 = mn0; mst1 = mn1;
        lst0 = lst0 * es0 + rs0;
        lst1 = lst1 * es1 + rs1;

        // P tile to smem (tf32-rounded); warp-private rows
#pragma unroll
        for (int nt = 0; nt < 8; nt++) {
            float2 w0 = make_float2(rna_tf32(s[nt][0]), rna_tf32(s[nt][1]));
            float2 w1 = make_float2(rna_tf32(s[nt][2]), rna_tf32(s[nt][3]));
            *(float2*)&Ps[(m0 + g) * FP_STRIDE + nt * 8 + 2 * c] = w0;
            *(float2*)&Ps[(m0 + g + 8) * FP_STRIDE + nt * 8 + 2 * c] = w1;
        }
        __syncthreads();

        // V tile (tf32-rounded), stride 136
#pragma unroll
        for (int it = 0; it < 16; it++) {
            int idx = tid + it * 128;
            int r = idx >> 5, sg = (idx & 31) << 2;
            float4 v = *(const float4*)
                &g_mixed[((size_t)((kb * 64 + r) * 2 + b)) * O_QKV + 4352 + grp * HDIM + sg];
            float* d = &KVs[r * FV_STRIDE + sg];
            d[0] = rna_tf32(v.x); d[1] = rna_tf32(v.y);
            d[2] = rna_tf32(v.z); d[3] = rna_tf32(v.w);
        }
        __syncthreads();

        // O = O*escale + P @ V
#pragma unroll
        for (int nt = 0; nt < 16; nt++) {
            o[nt][0] *= es0; o[nt][1] *= es0;
            o[nt][2] *= es1; o[nt][3] *= es1;
        }
#pragma unroll
        for (int kk = 0; kk < 8; kk++) {
            const int k8 = kk * 8;
            uint32_t a[4];
            a[0] = f2u(Ps[(m0 + g) * FP_STRIDE + k8 + c]);
            a[1] = f2u(Ps[(m0 + g + 8) * FP_STRIDE + k8 + c]);
            a[2] = f2u(Ps[(m0 + g) * FP_STRIDE + k8 + c + 4]);
            a[3] = f2u(Ps[(m0 + g + 8) * FP_STRIDE + k8 + c + 4]);
#pragma unroll
            for (int nt = 0; nt < 16; nt++) {
                uint32_t bfr[2];
                bfr[0] = f2u(KVs[(k8 + c) * FV_STRIDE + nt * 8 + g]);
                bfr[1] = f2u(KVs[(k8 + c + 4) * FV_STRIDE + nt * 8 + g]);
                mma8(o[nt], a, bfr);
            }
        }
    }

    // normalize + write ctx (tf32-rounded for the dense GEMM)
    const float inv0 = 1.f / lst0, inv1 = 1.f / lst1;
#pragma unroll
    for (int nt = 0; nt < 16; nt++) {
        const int ccol = h * HDIM + nt * 8 + 2 * c;
        size_t r0 = ((size_t)((qb * 64 + m0 + g) * 2 + b)) * H_DIM + ccol;
        size_t r1 = ((size_t)((qb * 64 + m0 + g + 8) * 2 + b)) * H_DIM + ccol;
        float2 v0 = make_float2(rna_tf32(o[nt][0] * inv0), rna_tf32(o[nt][1] * inv0));
        float2 v1 = make_float2(rna_tf32(o[nt][2] * inv1), rna_tf32(o[nt][3] * inv1));
        *(float2*)&g_ctx[r0] = v0;
        *(float2*)&g_ctx[r1] = v1;
    }
}

// ---------------------------------------------------------------------------
extern "C" void kernel_launch(void* const* d_in, const int* in_sizes, int n_in,
                              void* d_out, int out_size)
{
    const float* hidden = (const float*)d_in[0];
    const float* rope   = (const float*)d_in[2];
    const float* Wqkv   = (const float*)d_in[3];
    const float* bqkv   = (const float*)d_in[4];
    const float* Wd     = (const float*)d_in[5];
    float* out = (float*)d_out;

    float *mixed, *ctx, *hid, *wq, *wd;
    cudaGetSymbolAddress((void**)&mixed, g_mixed);
    cudaGetSymbolAddress((void**)&ctx,   g_ctx);
    cudaGetSymbolAddress((void**)&hid,   g_hid);
    cudaGetSymbolAddress((void**)&wq,    g_wq);
    cudaGetSymbolAddress((void**)&wd,    g_wd);

    cudaFuncSetAttribute(gemm_mma_kernel,
                         cudaFuncAttributeMaxDynamicSharedMemorySize, GEMM_SMEM);
    cudaFuncSetAttribute(flash_mma_kernel,
                         cudaFuncAttributeMaxDynamicSharedMemorySize, FLASH_SMEM);

    // tf32 pre-rounding (RNA)
    {
        int n4 = M_ROWS * H_DIM / 4;
        round_tf32_kernel<<<n4 / 256, 256>>>((const float4*)hidden, (float4*)hid, n4);
    }
    {
        int n4 = O_QKV * H_DIM / 4;
        round_tf32_kernel<<<n4 / 256, 256>>>((const float4*)Wqkv, (float4*)wq, n4);
    }
    {
        int n4 = H_DIM * H_DIM / 4;
        round_tf32_kernel<<<n4 / 256, 256>>>((const float4*)Wd, (float4*)wd, n4);
    }

    // 1) QKV projection + bias
    gemm_mma_kernel<<<dim3(O_QKV / 128, M_ROWS / 128), 256, GEMM_SMEM>>>(
        hid, wq, bqkv, mixed, O_QKV, H_DIM);

    // 2) RoPE
    const int total = S_LEN * B_SZ * (NHEADS + NGRP) * 32;
    rope_kernel<<<(total + 255) / 256, 256>>>(rope);

    // 3) flash attention (tensor cores)
    flash_mma_kernel<<<dim3(S_LEN / 64, NHEADS, B_SZ), 128, FLASH_SMEM>>>();

    // 4) dense projection
    gemm_mma_kernel<<<dim3(H_DIM / 128, M_ROWS / 128), 256, GEMM_SMEM>>>(
        ctx, wd, nullptr, out, H_DIM, H_DIM);
}

// round 5
// speedup vs baseline: 3.1706x; 1.6308x over previous
#include <cuda_runtime.h>
#include <math.h>
#include <stdint.h>

#define S_LEN  2048
#define B_SZ   2
#define H_DIM  4096
#define NHEADS 32
#define NGRP   2
#define HDIM   128
#define O_QKV  4608
#define M_ROWS 4096

// ---------------- scratch (__device__ globals; allocation-free rule) --------
__device__ float g_mixed[M_ROWS * O_QKV];
__device__ float g_ctx[M_ROWS * H_DIM];
__device__ float g_hid[M_ROWS * H_DIM];
__device__ float g_wq[O_QKV * H_DIM];
__device__ float g_wd[H_DIM * H_DIM];

// ---------------- helpers ----------------------------------------------------
__device__ __forceinline__ uint32_t smem_u32(const void* p) {
    uint32_t a;
    asm("{ .reg .u64 t; cvta.to.shared.u64 t, %1; cvt.u32.u64 %0, t; }" : "=r"(a) : "l"(p));
    return a;
}
__device__ __forceinline__ float rna_tf32(float x) {
    float r; asm("cvt.rna.tf32.f32 %0, %1;" : "=f"(r) : "f"(x)); return r;
}
__device__ __forceinline__ void cp_async16(uint32_t dst, const void* src) {
    asm volatile("cp.async.cg.shared.global [%0], [%1], 16;" :: "r"(dst), "l"(src));
}
__device__ __forceinline__ void cp_commit() {
    asm volatile("cp.async.commit_group;" ::: "memory");
}
template<int N> __device__ __forceinline__ void cp_wait() {
    asm volatile("cp.async.wait_group %0;" :: "n"(N) : "memory");
}
__device__ __forceinline__ void mma8(float* d, const uint32_t* a, const uint32_t* b) {
    asm volatile("mma.sync.aligned.m16n8k8.row.col.f32.tf32.tf32.f32 "
        "{%0,%1,%2,%3}, {%4,%5,%6,%7}, {%8,%9}, {%0,%1,%2,%3};"
        : "+f"(d[0]), "+f"(d[1]), "+f"(d[2]), "+f"(d[3])
        : "r"(a[0]), "r"(a[1]), "r"(a[2]), "r"(a[3]), "r"(b[0]), "r"(b[1]));
}
__device__ __forceinline__ uint32_t f2u(float x) { return __float_as_uint(x); }

// ---------------- tf32 rounding pass ----------------------------------------
__global__ __launch_bounds__(256) void round_tf32_kernel(
    const float4* __restrict__ in, float4* __restrict__ out, int n4)
{
    int i = blockIdx.x * blockDim.x + threadIdx.x;
    if (i >= n4) return;
    float4 v = in[i];
    v.x = rna_tf32(v.x); v.y = rna_tf32(v.y);
    v.z = rna_tf32(v.z); v.w = rna_tf32(v.w);
    out[i] = v;
}

// ---------------- mma.sync tf32 GEMM: C[M,N] = A[M,K] @ W[N,K]^T (+bias) ----
// CTA 128(M)x256(N), 256 thr, warp grid 2(M)x4(N), warp tile 64x64.
// K-chunk 32, 4-stage cp.async pipeline, ONE barrier per chunk.
// smem per stage: A 128x36 fl (18432 B) + B 256x36 fl (36864 B) = 55296 B.
#define GS        36
#define STG_FL    13824            // floats per stage (55296/4)
#define B_OFF_FL  4608             // A region floats per stage (128*36)
#define GSTAGES   4
#define GEMM_SMEM (GSTAGES * STG_FL * 4)   // 221184 B

__global__ __launch_bounds__(256, 1) void gemm_mma_kernel(
    const float* __restrict__ A, const float* __restrict__ W,
    const float* __restrict__ bias, float* __restrict__ C,
    int N, int K)
{
    extern __shared__ float sm[];
    const uint32_t sb = smem_u32(sm);

    const int tid = threadIdx.x;
    const int wid = tid >> 5, lid = tid & 31;
    const int g = lid >> 2, c = lid & 3;
    const int m0 = (wid & 1) * 64, n0 = (wid >> 1) * 64;
    const int row0 = blockIdx.y * 128;
    const int col0 = blockIdx.x * 256;

    float acc[4][8][4];
#pragma unroll
    for (int i = 0; i < 4; i++)
#pragma unroll
        for (int j = 0; j < 8; j++)
#pragma unroll
            for (int k = 0; k < 4; k++) acc[i][j][k] = 0.f;

    const int nchunk = K / 32;
    // A loader: 2 threads per row (4x16B each); B loader: 1 thread per row (8x16B)
    const int arow = tid >> 1;
    const int af0  = (tid & 1) * 16;

#define LOADCH(ch, st) do {                                                   \
        const float* _a = A + (size_t)(row0 + arow) * K + (ch) * 32 + af0;    \
        const float* _b = W + (size_t)(col0 + tid) * K + (ch) * 32;           \
        uint32_t _da = sb + (st) * (STG_FL * 4) + arow * 144 + af0 * 4;       \
        uint32_t _db = sb + (st) * (STG_FL * 4) + B_OFF_FL * 4 + tid * 144;   \
        cp_async16(_da,      _a);                                             \
        cp_async16(_da + 16, _a + 4);                                         \
        cp_async16(_da + 32, _a + 8);                                         \
        cp_async16(_da + 48, _a + 12);                                        \
        cp_async16(_db,       _b);                                            \
        cp_async16(_db + 16,  _b + 4);                                        \
        cp_async16(_db + 32,  _b + 8);                                        \
        cp_async16(_db + 48,  _b + 12);                                       \
        cp_async16(_db + 64,  _b + 16);                                       \
        cp_async16(_db + 80,  _b + 20);                                       \
        cp_async16(_db + 96,  _b + 24);                                       \
        cp_async16(_db + 112, _b + 28);                                       \
        cp_commit();                                                          \
    } while (0)

    LOADCH(0, 0);
    LOADCH(1, 1);

    for (int i = 0; i < nchunk; i++) {
        const int st = i & 3;
        if (i + 2 < nchunk) { LOADCH(i + 2, (i + 2) & 3); cp_wait<2>(); }
        else cp_wait<0>();
        __syncthreads();

        const float* as = sm + st * STG_FL;
        const float* bs = as + B_OFF_FL;
#pragma unroll
        for (int kk = 0; kk < 4; kk++) {
            const int k8 = kk * 8;
            uint32_t af[4][4], bf[8][2];
#pragma unroll
            for (int mt = 0; mt < 4; mt++) {
                const int r = m0 + mt * 16 + g;
                af[mt][0] = f2u(as[r * GS + k8 + c]);
                af[mt][1] = f2u(as[(r + 8) * GS + k8 + c]);
                af[mt][2] = f2u(as[r * GS + k8 + c + 4]);
                af[mt][3] = f2u(as[(r + 8) * GS + k8 + c + 4]);
            }
#pragma unroll
            for (int nt = 0; nt < 8; nt++) {
                const int cl = n0 + nt * 8 + g;
                bf[nt][0] = f2u(bs[cl * GS + k8 + c]);
                bf[nt][1] = f2u(bs[cl * GS + k8 + c + 4]);
            }
#pragma unroll
            for (int mt = 0; mt < 4; mt++)
#pragma unroll
                for (int nt = 0; nt < 8; nt++)
                    mma8(acc[mt][nt], af[mt], bf[nt]);
        }
    }
#undef LOADCH

    // epilogue
#pragma unroll
    for (int mt = 0; mt < 4; mt++) {
#pragma unroll
        for (int nt = 0; nt < 8; nt++) {
            const int rr = row0 + m0 + mt * 16 + g;
            const int cc = col0 + n0 + nt * 8 + 2 * c;
            float b0 = bias ? bias[cc] : 0.f;
            float b1 = bias ? bias[cc + 1] : 0.f;
            float2 v0 = make_float2(acc[mt][nt][0] + b0, acc[mt][nt][1] + b1);
            float2 v1 = make_float2(acc[mt][nt][2] + b0, acc[mt][nt][3] + b1);
            *(float2*)&C[(size_t)rr * N + cc]       = v0;
            *(float2*)&C[(size_t)(rr + 8) * N + cc] = v1;
        }
    }
}

// ---------------- RoPE in place on g_mixed ----------------------------------
__global__ __launch_bounds__(256) void rope_kernel(const float* __restrict__ rope)
{
    int idx = blockIdx.x * blockDim.x + threadIdx.x;
    const int TOTAL = S_LEN * B_SZ * (NHEADS + NGRP) * 32;
    if (idx >= TOTAL) return;
    int i  = idx & 31;
    int t  = idx >> 5;
    int hh = t % (NHEADS + NGRP);
    int sb = t / (NHEADS + NGRP);
    int s  = sb >> 1;

    size_t row = (size_t)sb * O_QKV;
    int off = (hh < NHEADS) ? hh * HDIM : (NHEADS * HDIM + (hh - NHEADS) * HDIM);

    float cc = rope[s * 64 + 2 * i];
    float sn = rope[s * 64 + 2 * i + 1];
    float x0 = g_mixed[row + off + 2 * i];
    float x1 = g_mixed[row + off + 2 * i + 1];
    g_mixed[row + off + 2 * i]     = x0 * cc - x1 * sn;
    g_mixed[row + off + 2 * i + 1] = x1 * cc + x0 * sn;
}

// ---------------- flash attention with mma.sync (tf32), BQ=128 --------------
// 256 thr / 8 warps; warp w owns Q rows [w*16, w*16+16) x full 64-col S tile.
// smem: Qs[128][132], KV buffer (K stride 132 / V stride 136), Ps[128][68].
#define FQ_STRIDE 132
#define FV_STRIDE 136
#define FP_STRIDE 68
#define F_KVOFF 16896         // 128*132
#define F_POFF  25600         // + 64*136 = 8704
#define FLASH_SMEM ((25600 + 128 * FP_STRIDE) * 4)   // 137216 B

__global__ __launch_bounds__(256, 1) void flash_mma_kernel()
{
    extern __shared__ float sm[];
    float* Qs  = sm;
    float* KVs = sm + F_KVOFF;
    float* Ps  = sm + F_POFF;

    const int qb = blockIdx.x, h = blockIdx.y, b = blockIdx.z;
    const int grp = h >> 4;
    const int tid = threadIdx.x, wid = tid >> 5, lid = tid & 31;
    const int g = lid >> 2, c = lid & 3;
    const int m0 = wid * 16;
    const float scale = 0.08838834764831843f;

    // Q tile (scaled + tf32-rounded): 128 rows x 128 dims
#pragma unroll
    for (int it = 0; it < 16; it++) {
        int idx = tid + it * 256;
        int r = idx >> 5, sg = (idx & 31) << 2;
        float4 v = *(const float4*)
            &g_mixed[((size_t)((qb * 128 + r) * 2 + b)) * O_QKV + h * HDIM + sg];
        float* d = &Qs[r * FQ_STRIDE + sg];
        d[0] = rna_tf32(v.x * scale); d[1] = rna_tf32(v.y * scale);
        d[2] = rna_tf32(v.z * scale); d[3] = rna_tf32(v.w * scale);
    }

    float o[16][4];
#pragma unroll
    for (int nt = 0; nt < 16; nt++)
#pragma unroll
        for (int j = 0; j < 4; j++) o[nt][j] = 0.f;
    float mst0 = -INFINITY, mst1 = -INFINITY, lst0 = 0.f, lst1 = 0.f;

    const int nkb = 2 * qb + 2;          // key blocks of 64
    for (int kb = 0; kb < nkb; kb++) {
        __syncthreads();
        // K tile: 64 rows x 128 dims, stride 132
#pragma unroll
        for (int it = 0; it < 8; it++) {
            int idx = tid + it * 256;
            int r = idx >> 5, sg = (idx & 31) << 2;
            float4 v = *(const float4*)
                &g_mixed[((size_t)((kb * 64 + r) * 2 + b)) * O_QKV + 4096 + grp * HDIM + sg];
            float* d = &KVs[r * FQ_STRIDE + sg];
            d[0] = rna_tf32(v.x); d[1] = rna_tf32(v.y);
            d[2] = rna_tf32(v.z); d[3] = rna_tf32(v.w);
        }
        __syncthreads();

        // S = Q @ K^T  (warp: 16 rows x 64 cols)
        float s[8][4];
#pragma unroll
        for (int nt = 0; nt < 8; nt++)
#pragma unroll
            for (int j = 0; j < 4; j++) s[nt][j] = 0.f;

#pragma unroll
        for (int kk = 0; kk < 16; kk++) {
            const int k8 = kk * 8;
            uint32_t a[4];
            a[0] = f2u(Qs[(m0 + g) * FQ_STRIDE + k8 + c]);
            a[1] = f2u(Qs[(m0 + g + 8) * FQ_STRIDE + k8 + c]);
            a[2] = f2u(Qs[(m0 + g) * FQ_STRIDE + k8 + c + 4]);
            a[3] = f2u(Qs[(m0 + g + 8) * FQ_STRIDE + k8 + c + 4]);
#pragma unroll
            for (int nt = 0; nt < 8; nt++) {
                uint32_t bfr[2];
                bfr[0] = f2u(KVs[(nt * 8 + g) * FQ_STRIDE + k8 + c]);
                bfr[1] = f2u(KVs[(nt * 8 + g) * FQ_STRIDE + k8 + c + 4]);
                mma8(s[nt], a, bfr);
            }
        }

        if (kb >= 2 * qb) {        // diagonal region: causal mask
            const int r0 = qb * 128 + m0 + g, r1 = r0 + 8;
            const int cb = kb * 64;
#pragma unroll
            for (int nt = 0; nt < 8; nt++) {
                const int n = cb + nt * 8 + 2 * c;
                if (n > r0)     s[nt][0] = -1e30f;
                if (n + 1 > r0) s[nt][1] = -1e30f;
                if (n > r1)     s[nt][2] = -1e30f;
                if (n + 1 > r1) s[nt][3] = -1e30f;
            }
        }

        // online softmax
        float rm0 = -INFINITY, rm1 = -INFINITY;
#pragma unroll
        for (int nt = 0; nt < 8; nt++) {
            rm0 = fmaxf(rm0, fmaxf(s[nt][0], s[nt][1]));
            rm1 = fmaxf(rm1, fmaxf(s[nt][2], s[nt][3]));
        }
        rm0 = fmaxf(rm0, __shfl_xor_sync(0xffffffffu, rm0, 1));
        rm0 = fmaxf(rm0, __shfl_xor_sync(0xffffffffu, rm0, 2));
        rm1 = fmaxf(rm1, __shfl_xor_sync(0xffffffffu, rm1, 1));
        rm1 = fmaxf(rm1, __shfl_xor_sync(0xffffffffu, rm1, 2));
        const float mn0 = fmaxf(mst0, rm0);
        const float mn1 = fmaxf(mst1, rm1);
        const float es0 = __expf(mst0 - mn0);
        const float es1 = __expf(mst1 - mn1);
        float rs0 = 0.f, rs1 = 0.f;
#pragma unroll
        for (int nt = 0; nt < 8; nt++) {
            s[nt][0] = __expf(s[nt][0] - mn0);
            s[nt][1] = __expf(s[nt][1] - mn0);
            s[nt][2] = __expf(s[nt][2] - mn1);
            s[nt][3] = __expf(s[nt][3] - mn1);
            rs0 += s[nt][0] + s[nt][1];
            rs1 += s[nt][2] + s[nt][3];
        }
        rs0 += __shfl_xor_sync(0xffffffffu, rs0, 1);
        rs0 += __shfl_xor_sync(0xffffffffu, rs0, 2);
        rs1 += __shfl_xor_sync(0xffffffffu, rs1, 1);
        rs1 += __shfl_xor_sync(0xffffffffu, rs1, 2);
        mst0 = mn0; mst1 = mn1;
        lst0 = lst0 * es0 + rs0;
        lst1 = lst1 * es1 + rs1;

        // P tile to smem (tf32-rounded); warp-private rows
#pragma unroll
        for (int nt = 0; nt < 8; nt++) {
            float2 w0 = make_float2(rna_tf32(s[nt][0]), rna_tf32(s[nt][1]));
            float2 w1 = make_float2(rna_tf32(s[nt][2]), rna_tf32(s[nt][3]));
            *(float2*)&Ps[(m0 + g) * FP_STRIDE + nt * 8 + 2 * c] = w0;
            *(float2*)&Ps[(m0 + g + 8) * FP_STRIDE + nt * 8 + 2 * c] = w1;
        }
        __syncthreads();

        // V tile: 64 rows x 128 dims, stride 136
#pragma unroll
        for (int it = 0; it < 8; it++) {
            int idx = tid + it * 256;
            int r = idx >> 5, sg = (idx & 31) << 2;
            float4 v = *(const float4*)
                &g_mixed[((size_t)((kb * 64 + r) * 2 + b)) * O_QKV + 4352 + grp * HDIM + sg];
            float* d = &KVs[r * FV_STRIDE + sg];
            d[0] = rna_tf32(v.x); d[1] = rna_tf32(v.y);
            d[2] = rna_tf32(v.z); d[3] = rna_tf32(v.w);
        }
        __syncthreads();

        // O = O*escale + P @ V
#pragma unroll
        for (int nt = 0; nt < 16; nt++) {
            o[nt][0] *= es0; o[nt][1] *= es0;
            o[nt][2] *= es1; o[nt][3] *= es1;
        }
#pragma unroll
        for (int kk = 0; kk < 8; kk++) {
            const int k8 = kk * 8;
            uint32_t a[4];
            a[0] = f2u(Ps[(m0 + g) * FP_STRIDE + k8 + c]);
            a[1] = f2u(Ps[(m0 + g + 8) * FP_STRIDE + k8 + c]);
            a[2] = f2u(Ps[(m0 + g) * FP_STRIDE + k8 + c + 4]);
            a[3] = f2u(Ps[(m0 + g + 8) * FP_STRIDE + k8 + c + 4]);
#pragma unroll
            for (int nt = 0; nt < 16; nt++) {
                uint32_t bfr[2];
                bfr[0] = f2u(KVs[(k8 + c) * FV_STRIDE + nt * 8 + g]);
                bfr[1] = f2u(KVs[(k8 + c + 4) * FV_STRIDE + nt * 8 + g]);
                mma8(o[nt], a, bfr);
            }
        }
    }

    // normalize + write ctx (tf32-rounded for the dense GEMM)
    const float inv0 = 1.f / lst0, inv1 = 1.f / lst1;
#pragma unroll
    for (int nt = 0; nt < 16; nt++) {
        const int ccol = h * HDIM + nt * 8 + 2 * c;
        size_t r0 = ((size_t)((qb * 128 + m0 + g) * 2 + b)) * H_DIM + ccol;
        size_t r1 = ((size_t)((qb * 128 + m0 + g + 8) * 2 + b)) * H_DIM + ccol;
        float2 v0 = make_float2(rna_tf32(o[nt][0] * inv0), rna_tf32(o[nt][1] * inv0));
        float2 v1 = make_float2(rna_tf32(o[nt][2] * inv1), rna_tf32(o[nt][3] * inv1));
        *(float2*)&g_ctx[r0] = v0;
        *(float2*)&g_ctx[r1] = v1;
    }
}

// ---------------------------------------------------------------------------
extern "C" void kernel_launch(void* const* d_in, const int* in_sizes, int n_in,
                              void* d_out, int out_size)
{
    const float* hidden = (const float*)d_in[0];
    const float* rope   = (const float*)d_in[2];
    const float* Wqkv   = (const float*)d_in[3];
    const float* bqkv   = (const float*)d_in[4];
    const float* Wd     = (const float*)d_in[5];
    float* out = (float*)d_out;

    float *mixed, *ctx, *hid, *wq, *wd;
    cudaGetSymbolAddress((void**)&mixed, g_mixed);
    cudaGetSymbolAddress((void**)&ctx,   g_ctx);
    cudaGetSymbolAddress((void**)&hid,   g_hid);
    cudaGetSymbolAddress((void**)&wq,    g_wq);
    cudaGetSymbolAddress((void**)&wd,    g_wd);

    cudaFuncSetAttribute(gemm_mma_kernel,
                         cudaFuncAttributeMaxDynamicSharedMemorySize, GEMM_SMEM);
    cudaFuncSetAttribute(flash_mma_kernel,
                         cudaFuncAttributeMaxDynamicSharedMemorySize, FLASH_SMEM);

    // tf32 pre-rounding (RNA)
    {
        int n4 = M_ROWS * H_DIM / 4;
        round_tf32_kernel<<<n4 / 256, 256>>>((const float4*)hidden, (float4*)hid, n4);
    }
    {
        int n4 = O_QKV * H_DIM / 4;
        round_tf32_kernel<<<n4 / 256, 256>>>((const float4*)Wqkv, (float4*)wq, n4);
    }
    {
        int n4 = H_DIM * H_DIM / 4;
        round_tf32_kernel<<<n4 / 256, 256>>>((const float4*)Wd, (float4*)wd, n4);
    }

    // 1) QKV projection + bias
    gemm_mma_kernel<<<dim3(O_QKV / 256, M_ROWS / 128), 256, GEMM_SMEM>>>(
        hid, wq, bqkv, mixed, O_QKV, H_DIM);

    // 2) RoPE
    const int total = S_LEN * B_SZ * (NHEADS + NGRP) * 32;
    rope_kernel<<<(total + 255) / 256, 256>>>(rope);

    // 3) flash attention (tensor cores, BQ=128)
    flash_mma_kernel<<<dim3(S_LEN / 128, NHEADS, B_SZ), 256, FLASH_SMEM>>>();

    // 4) dense projection
    gemm_mma_kernel<<<dim3(H_DIM / 256, M_ROWS / 128), 256, GEMM_SMEM>>>(
        ctx, wd, nullptr, out, H_DIM, H_DIM);
}

// round 7
// speedup vs baseline: 3.2507x; 1.0253x over previous
#include <cuda_runtime.h>
#include <math.h>
#include <stdint.h>

#define S_LEN  2048
#define B_SZ   2
#define H_DIM  4096
#define NHEADS 32
#define NGRP   2
#define HDIM   128
#define O_QKV  4608
#define M_ROWS 4096

// ---------------- scratch (__device__ globals; allocation-free rule) --------
__device__ float g_mixed[M_ROWS * O_QKV];
__device__ float g_ctx[M_ROWS * H_DIM];
__device__ float g_hid[M_ROWS * H_DIM];
__device__ float g_wq[O_QKV * H_DIM];
__device__ float g_wd[H_DIM * H_DIM];

// ---------------- helpers ----------------------------------------------------
__device__ __forceinline__ uint32_t smem_u32(const void* p) {
    uint32_t a;
    asm("{ .reg .u64 t; cvta.to.shared.u64 t, %1; cvt.u32.u64 %0, t; }" : "=r"(a) : "l"(p));
    return a;
}
__device__ __forceinline__ float rna_tf32(float x) {
    float r; asm("cvt.rna.tf32.f32 %0, %1;" : "=f"(r) : "f"(x)); return r;
}
__device__ __forceinline__ void cp_async16(uint32_t dst, const void* src) {
    asm volatile("cp.async.cg.shared.global [%0], [%1], 16;" :: "r"(dst), "l"(src));
}
__device__ __forceinline__ void cp_commit() {
    asm volatile("cp.async.commit_group;" ::: "memory");
}
template<int N> __device__ __forceinline__ void cp_wait() {
    asm volatile("cp.async.wait_group %0;" :: "n"(N) : "memory");
}
__device__ __forceinline__ void mma8(float* d, const uint32_t* a, const uint32_t* b) {
    asm volatile("mma.sync.aligned.m16n8k8.row.col.f32.tf32.tf32.f32 "
        "{%0,%1,%2,%3}, {%4,%5,%6,%7}, {%8,%9}, {%0,%1,%2,%3};"
        : "+f"(d[0]), "+f"(d[1]), "+f"(d[2]), "+f"(d[3])
        : "r"(a[0]), "r"(a[1]), "r"(a[2]), "r"(a[3]), "r"(b[0]), "r"(b[1]));
}
__device__ __forceinline__ uint32_t f2u(float x) { return __float_as_uint(x); }

// ---------------- tf32 rounding pass ----------------------------------------
__global__ __launch_bounds__(256) void round_tf32_kernel(
    const float4* __restrict__ in, float4* __restrict__ out, int n4)
{
    int i = blockIdx.x * blockDim.x + threadIdx.x;
    if (i >= n4) return;
    float4 v = in[i];
    v.x = rna_tf32(v.x); v.y = rna_tf32(v.y);
    v.z = rna_tf32(v.z); v.w = rna_tf32(v.w);
    out[i] = v;
}

// ---------------- mma.sync tf32 GEMM: C[M,N] = A[M,K] @ W[N,K]^T (+bias) ----
// CTA 128(M)x256(N), 256 thr, warp grid 2(M)x4(N), warp tile 64x64.
// K-chunk 32, 4-stage cp.async pipeline, ONE barrier per chunk.
#define GS        36
#define STG_FL    13824
#define B_OFF_FL  4608
#define GSTAGES   4
#define GEMM_SMEM (GSTAGES * STG_FL * 4)   // 221184 B

__global__ __launch_bounds__(256, 1) void gemm_mma_kernel(
    const float* __restrict__ A, const float* __restrict__ W,
    const float* __restrict__ bias, float* __restrict__ C,
    int N, int K, int round_out)
{
    extern __shared__ float sm[];
    const uint32_t sb = smem_u32(sm);

    const int tid = threadIdx.x;
    const int wid = tid >> 5, lid = tid & 31;
    const int g = lid >> 2, c = lid & 3;
    const int m0 = (wid & 1) * 64, n0 = (wid >> 1) * 64;
    const int row0 = blockIdx.y * 128;
    const int col0 = blockIdx.x * 256;

    float acc[4][8][4];
#pragma unroll
    for (int i = 0; i < 4; i++)
#pragma unroll
        for (int j = 0; j < 8; j++)
#pragma unroll
            for (int k = 0; k < 4; k++) acc[i][j][k] = 0.f;

    const int nchunk = K / 32;
    const int arow = tid >> 1;
    const int af0  = (tid & 1) * 16;

#define LOADCH(ch, st) do {                                                   \
        const float* _a = A + (size_t)(row0 + arow) * K + (ch) * 32 + af0;    \
        const float* _b = W + (size_t)(col0 + tid) * K + (ch) * 32;           \
        uint32_t _da = sb + (st) * (STG_FL * 4) + arow * 144 + af0 * 4;       \
        uint32_t _db = sb + (st) * (STG_FL * 4) + B_OFF_FL * 4 + tid * 144;   \
        cp_async16(_da,      _a);                                             \
        cp_async16(_da + 16, _a + 4);                                         \
        cp_async16(_da + 32, _a + 8);                                         \
        cp_async16(_da + 48, _a + 12);                                        \
        cp_async16(_db,       _b);                                            \
        cp_async16(_db + 16,  _b + 4);                                        \
        cp_async16(_db + 32,  _b + 8);                                        \
        cp_async16(_db + 48,  _b + 12);                                       \
        cp_async16(_db + 64,  _b + 16);                                       \
        cp_async16(_db + 80,  _b + 20);                                       \
        cp_async16(_db + 96,  _b + 24);                                       \
        cp_async16(_db + 112, _b + 28);                                       \
        cp_commit();                                                          \
    } while (0)

    LOADCH(0, 0);
    LOADCH(1, 1);

    for (int i = 0; i < nchunk; i++) {
        const int st = i & 3;
        if (i + 2 < nchunk) { LOADCH(i + 2, (i + 2) & 3); cp_wait<2>(); }
        else cp_wait<0>();
        __syncthreads();

        const float* as = sm + st * STG_FL;
        const float* bs = as + B_OFF_FL;
#pragma unroll
        for (int kk = 0; kk < 4; kk++) {
            const int k8 = kk * 8;
            uint32_t af[4][4], bf[8][2];
#pragma unroll
            for (int mt = 0; mt < 4; mt++) {
                const int r = m0 + mt * 16 + g;
                af[mt][0] = f2u(as[r * GS + k8 + c]);
                af[mt][1] = f2u(as[(r + 8) * GS + k8 + c]);
                af[mt][2] = f2u(as[r * GS + k8 + c + 4]);
                af[mt][3] = f2u(as[(r + 8) * GS + k8 + c + 4]);
            }
#pragma unroll
            for (int nt = 0; nt < 8; nt++) {
                const int cl = n0 + nt * 8 + g;
                bf[nt][0] = f2u(bs[cl * GS + k8 + c]);
                bf[nt][1] = f2u(bs[cl * GS + k8 + c + 4]);
            }
#pragma unroll
            for (int mt = 0; mt < 4; mt++)
#pragma unroll
                for (int nt = 0; nt < 8; nt++)
                    mma8(acc[mt][nt], af[mt], bf[nt]);
        }
    }
#undef LOADCH

    // epilogue (optionally tf32-rounded output)
#pragma unroll
    for (int mt = 0; mt < 4; mt++) {
#pragma unroll
        for (int nt = 0; nt < 8; nt++) {
            const int rr = row0 + m0 + mt * 16 + g;
            const int cc = col0 + n0 + nt * 8 + 2 * c;
            float b0 = bias ? bias[cc] : 0.f;
            float b1 = bias ? bias[cc + 1] : 0.f;
            float v00 = acc[mt][nt][0] + b0, v01 = acc[mt][nt][1] + b1;
            float v10 = acc[mt][nt][2] + b0, v11 = acc[mt][nt][3] + b1;
            if (round_out) {
                v00 = rna_tf32(v00); v01 = rna_tf32(v01);
                v10 = rna_tf32(v10); v11 = rna_tf32(v11);
            }
            *(float2*)&C[(size_t)rr * N + cc]       = make_float2(v00, v01);
            *(float2*)&C[(size_t)(rr + 8) * N + cc] = make_float2(v10, v11);
        }
    }
}

// ---------------- RoPE in place on g_mixed (tf32-rounded outputs) -----------
__global__ __launch_bounds__(256) void rope_kernel(const float* __restrict__ rope)
{
    int idx = blockIdx.x * blockDim.x + threadIdx.x;
    const int TOTAL = S_LEN * B_SZ * (NHEADS + NGRP) * 32;
    if (idx >= TOTAL) return;
    int i  = idx & 31;
    int t  = idx >> 5;
    int hh = t % (NHEADS + NGRP);
    int sb = t / (NHEADS + NGRP);
    int s  = sb >> 1;

    size_t row = (size_t)sb * O_QKV;
    int off = (hh < NHEADS) ? hh * HDIM : (NHEADS * HDIM + (hh - NHEADS) * HDIM);

    float cc = rope[s * 64 + 2 * i];
    float sn = rope[s * 64 + 2 * i + 1];
    float x0 = g_mixed[row + off + 2 * i];
    float x1 = g_mixed[row + off + 2 * i + 1];
    g_mixed[row + off + 2 * i]     = rna_tf32(x0 * cc - x1 * sn);
    g_mixed[row + off + 2 * i + 1] = rna_tf32(x1 * cc + x0 * sn);
}

// ---------------- flash attention, pipelined (tf32 mma), BQ=128 --------------
// 256 thr / 8 warps; warp w owns Q rows [w*16, w*16+16).
// Q fragments in registers; K/V double-buffered via cp.async; 1 barrier/iter.
// smem floats: K0@0 (64x132), K1@8448, V0@16896 (64x136), V1@25600, Ps@34304 (128x68)
#define FK_STRIDE 132
#define FV_STRIDE 136
#define FP_STRIDE 68
#define KBUF0 0
#define KBUF1 8448
#define VBUF0 16896
#define VBUF1 25600
#define PSOFF 34304
#define FLASH_SMEM ((PSOFF + 128 * FP_STRIDE) * 4)   // 172032 B

__global__ __launch_bounds__(256, 1) void flash_mma_kernel()
{
    extern __shared__ float sm[];
    const uint32_t sbase = smem_u32(sm);
    float* Ps = sm + PSOFF;

    const int qb = blockIdx.x, h = blockIdx.y, b = blockIdx.z;
    const int grp = h >> 4;
    const int tid = threadIdx.x, wid = tid >> 5, lid = tid & 31;
    const int g = lid >> 2, c = lid & 3;
    const int m0 = wid * 16;
    const float scale = 0.08838834764831843f;

    // K-tile loader: 64 rows x 128 floats = 2048 16B-segments (8 per thread)
#define LOADK(kb, p) do {                                                      \
        _Pragma("unroll")                                                      \
        for (int _s = 0; _s < 8; _s++) {                                       \
            int _ln = tid + _s * 256;                                          \
            int _r = _ln >> 5, _c = _ln & 31;                                  \
            cp_async16(sbase + ((p) ? KBUF1 : KBUF0) * 4 + _r * 528 + _c * 16, \
                &g_mixed[((size_t)(((kb) * 64 + _r) * 2 + b)) * O_QKV          \
                         + 4096 + grp * HDIM + _c * 4]);                       \
        } } while (0)
    // V-tile loader (stride 136 fl)
#define LOADV(kb, p) do {                                                      \
        _Pragma("unroll")                                                      \
        for (int _s = 0; _s < 8; _s++) {                                       \
            int _ln = tid + _s * 256;                                          \
            int _r = _ln >> 5, _c = _ln & 31;                                  \
            cp_async16(sbase + ((p) ? VBUF1 : VBUF0) * 4 + _r * 544 + _c * 16, \
                &g_mixed[((size_t)(((kb) * 64 + _r) * 2 + b)) * O_QKV          \
                         + 4352 + grp * HDIM + _c * 4]);                       \
        } } while (0)

    // ---- stage Q (128 rows x 32 segs = 4096 segments) through K0/K1
#pragma unroll
    for (int s = 0; s < 16; s++) {
        int ln = tid + s * 256;            // 0..4095
        int r = ln >> 5, cseg = ln & 31;
        uint32_t dst = (r < 64) ? (sbase + KBUF0 * 4 + r * 528 + cseg * 16)
                                : (sbase + KBUF1 * 4 + (r - 64) * 528 + cseg * 16);
        cp_async16(dst, &g_mixed[((size_t)((qb * 128 + r) * 2 + b)) * O_QKV
                                 + h * HDIM + cseg * 4]);
    }
    cp_commit();
    cp_wait<0>();
    __syncthreads();

    uint32_t qf[16][4];
    {
        const float* qsrc = sm + ((wid < 4) ? KBUF0 : KBUF1);
        const int rl = (m0 & 63) + g;
#pragma unroll
        for (int kk = 0; kk < 16; kk++) {
            const int k8 = kk * 8;
            qf[kk][0] = f2u(qsrc[rl * FK_STRIDE + k8 + c]);
            qf[kk][1] = f2u(qsrc[(rl + 8) * FK_STRIDE + k8 + c]);
            qf[kk][2] = f2u(qsrc[rl * FK_STRIDE + k8 + c + 4]);
            qf[kk][3] = f2u(qsrc[(rl + 8) * FK_STRIDE + k8 + c + 4]);
        }
    }
    __syncthreads();   // all warps done reading K bufs before K0/V0 load

    float o[16][4];
#pragma unroll
    for (int nt = 0; nt < 16; nt++)
#pragma unroll
        for (int j = 0; j < 4; j++) o[nt][j] = 0.f;
    float mst0 = -INFINITY, mst1 = -INFINITY, lst0 = 0.f, lst1 = 0.f;

    const int nkb = 2 * qb + 2;
    LOADK(0, 0); LOADV(0, 0); cp_commit();

    for (int kb = 0; kb < nkb; kb++) {
        const int p = kb & 1;
        cp_wait<0>();
        __syncthreads();   // kb data visible; all warps done with kb-1 buffers
        if (kb + 1 < nkb) { LOADK(kb + 1, p ^ 1); LOADV(kb + 1, p ^ 1); cp_commit(); }

        const float* Ks = sm + (p ? KBUF1 : KBUF0);
        const float* Vs = sm + (p ? VBUF1 : VBUF0);

        // S = Q @ K^T
        float s[8][4];
#pragma unroll
        for (int nt = 0; nt < 8; nt++)
#pragma unroll
            for (int j = 0; j < 4; j++) s[nt][j] = 0.f;
#pragma unroll
        for (int kk = 0; kk < 16; kk++) {
            const int k8 = kk * 8;
#pragma unroll
            for (int nt = 0; nt < 8; nt++) {
                uint32_t bfr[2];
                bfr[0] = f2u(Ks[(nt * 8 + g) * FK_STRIDE + k8 + c]);
                bfr[1] = f2u(Ks[(nt * 8 + g) * FK_STRIDE + k8 + c + 4]);
                mma8(s[nt], qf[kk], bfr);
            }
        }

        if (kb >= 2 * qb) {        // causal mask (diagonal region)
            const int r0 = qb * 128 + m0 + g, r1 = r0 + 8;
            const int cb = kb * 64;
#pragma unroll
            for (int nt = 0; nt < 8; nt++) {
                const int n = cb + nt * 8 + 2 * c;
                if (n > r0)     s[nt][0] = -1e30f;
                if (n + 1 > r0) s[nt][1] = -1e30f;
                if (n > r1)     s[nt][2] = -1e30f;
                if (n + 1 > r1) s[nt][3] = -1e30f;
            }
        }

        // online softmax with folded scale: p = exp((s - m) * scale)
        float rm0 = -INFINITY, rm1 = -INFINITY;
#pragma unroll
        for (int nt = 0; nt < 8; nt++) {
            rm0 = fmaxf(rm0, fmaxf(s[nt][0], s[nt][1]));
            rm1 = fmaxf(rm1, fmaxf(s[nt][2], s[nt][3]));
        }
        rm0 = fmaxf(rm0, __shfl_xor_sync(0xffffffffu, rm0, 1));
        rm0 = fmaxf(rm0, __shfl_xor_sync(0xffffffffu, rm0, 2));
        rm1 = fmaxf(rm1, __shfl_xor_sync(0xffffffffu, rm1, 1));
        rm1 = fmaxf(rm1, __shfl_xor_sync(0xffffffffu, rm1, 2));
        const float mn0 = fmaxf(mst0, rm0);
        const float mn1 = fmaxf(mst1, rm1);
        const float es0 = __expf((mst0 - mn0) * scale);
        const float es1 = __expf((mst1 - mn1) * scale);
        float rs0 = 0.f, rs1 = 0.f;
#pragma unroll
        for (int nt = 0; nt < 8; nt++) {
            s[nt][0] = __expf((s[nt][0] - mn0) * scale);
            s[nt][1] = __expf((s[nt][1] - mn0) * scale);
            s[nt][2] = __expf((s[nt][2] - mn1) * scale);
            s[nt][3] = __expf((s[nt][3] - mn1) * scale);
            rs0 += s[nt][0] + s[nt][1];
            rs1 += s[nt][2] + s[nt][3];
        }
        rs0 += __shfl_xor_sync(0xffffffffu, rs0, 1);
        rs0 += __shfl_xor_sync(0xffffffffu, rs0, 2);
        rs1 += __shfl_xor_sync(0xffffffffu, rs1, 1);
        rs1 += __shfl_xor_sync(0xffffffffu, rs1, 2);
        mst0 = mn0; mst1 = mn1;
        lst0 = lst0 * es0 + rs0;
        lst1 = lst1 * es1 + rs1;

        // P tile to smem (warp-private rows: no CTA barrier needed)
#pragma unroll
        for (int nt = 0; nt < 8; nt++) {
            float2 w0 = make_float2(rna_tf32(s[nt][0]), rna_tf32(s[nt][1]));
            float2 w1 = make_float2(rna_tf32(s[nt][2]), rna_tf32(s[nt][3]));
            *(float2*)&Ps[(m0 + g) * FP_STRIDE + nt * 8 + 2 * c] = w0;
            *(float2*)&Ps[(m0 + g + 8) * FP_STRIDE + nt * 8 + 2 * c] = w1;
        }
        __syncwarp();

        // O = O*escale + P @ V
#pragma unroll
        for (int nt = 0; nt < 16; nt++) {
            o[nt][0] *= es0; o[nt][1] *= es0;
            o[nt][2] *= es1; o[nt][3] *= es1;
        }
#pragma unroll
        for (int kk = 0; kk < 8; kk++) {
            const int k8 = kk * 8;
            uint32_t a[4];
            a[0] = f2u(Ps[(m0 + g) * FP_STRIDE + k8 + c]);
            a[1] = f2u(Ps[(m0 + g + 8) * FP_STRIDE + k8 + c]);
            a[2] = f2u(Ps[(m0 + g) * FP_STRIDE + k8 + c + 4]);
            a[3] = f2u(Ps[(m0 + g + 8) * FP_STRIDE + k8 + c + 4]);
#pragma unroll
            for (int nt = 0; nt < 16; nt++) {
                uint32_t bfr[2];
                bfr[0] = f2u(Vs[(k8 + c) * FV_STRIDE + nt * 8 + g]);
                bfr[1] = f2u(Vs[(k8 + c + 4) * FV_STRIDE + nt * 8 + g]);
                mma8(o[nt], a, bfr);
            }
        }
    }
#undef LOADK
#undef LOADV

    // normalize + write ctx (tf32-rounded for the dense GEMM)
    const float inv0 = 1.f / lst0, inv1 = 1.f / lst1;
#pragma unroll
    for (int nt = 0; nt < 16; nt++) {
        const int ccol = h * HDIM + nt * 8 + 2 * c;
        size_t r0 = ((size_t)((qb * 128 + m0 + g) * 2 + b)) * H_DIM + ccol;
        size_t r1 = ((size_t)((qb * 128 + m0 + g + 8) * 2 + b)) * H_DIM + ccol;
        float2 v0 = make_float2(rna_tf32(o[nt][0] * inv0), rna_tf32(o[nt][1] * inv0));
        float2 v1 = make_float2(rna_tf32(o[nt][2] * inv1), rna_tf32(o[nt][3] * inv1));
        *(float2*)&g_ctx[r0] = v0;
        *(float2*)&g_ctx[r1] = v1;
    }
}

// ---------------------------------------------------------------------------
extern "C" void kernel_launch(void* const* d_in, const int* in_sizes, int n_in,
                              void* d_out, int out_size)
{
    const float* hidden = (const float*)d_in[0];
    const float* rope   = (const float*)d_in[2];
    const float* Wqkv   = (const float*)d_in[3];
    const float* bqkv   = (const float*)d_in[4];
    const float* Wd     = (const float*)d_in[5];
    float* out = (float*)d_out;

    float *mixed, *ctx, *hid, *wq, *wd;
    cudaGetSymbolAddress((void**)&mixed, g_mixed);
    cudaGetSymbolAddress((void**)&ctx,   g_ctx);
    cudaGetSymbolAddress((void**)&hid,   g_hid);
    cudaGetSymbolAddress((void**)&wq,    g_wq);
    cudaGetSymbolAddress((void**)&wd,    g_wd);

    cudaFuncSetAttribute(gemm_mma_kernel,
                         cudaFuncAttributeMaxDynamicSharedMemorySize, GEMM_SMEM);
    cudaFuncSetAttribute(flash_mma_kernel,
                         cudaFuncAttributeMaxDynamicSharedMemorySize, FLASH_SMEM);

    // tf32 pre-rounding (RNA) of GEMM inputs
    {
        int n4 = M_ROWS * H_DIM / 4;
        round_tf32_kernel<<<n4 / 256, 256>>>((const float4*)hidden, (float4*)hid, n4);
    }
    {
        int n4 = O_QKV * H_DIM / 4;
        round_tf32_kernel<<<n4 / 256, 256>>>((const float4*)Wqkv, (float4*)wq, n4);
    }
    {
        int n4 = H_DIM * H_DIM / 4;
        round_tf32_kernel<<<n4 / 256, 256>>>((const float4*)Wd, (float4*)wd, n4);
    }

    // 1) QKV projection + bias (tf32-rounded output -> flash consumes directly)
    gemm_mma_kernel<<<dim3(O_QKV / 256, M_ROWS / 128), 256, GEMM_SMEM>>>(
        hid, wq, bqkv, mixed, O_QKV, H_DIM, 1);

    // 2) RoPE (rounded outputs)
    const int total = S_LEN * B_SZ * (NHEADS + NGRP) * 32;
    rope_kernel<<<(total + 255) / 256, 256>>>(rope);

    // 3) flash attention (pipelined)
    flash_mma_kernel<<<dim3(S_LEN / 128, NHEADS, B_SZ), 256, FLASH_SMEM>>>();

    // 4) dense projection (fp32 output)
    gemm_mma_kernel<<<dim3(H_DIM / 256, M_ROWS / 128), 256, GEMM_SMEM>>>(
        ctx, wd, nullptr, out, H_DIM, H_DIM, 0);
}

// round 9
// speedup vs baseline: 6.8545x; 2.1086x over previous
#include <cuda_runtime.h>
#include <cuda_fp16.h>
#include <math.h>
#include <stdint.h>

#define S_LEN  2048
#define B_SZ   2
#define H_DIM  4096
#define NHEADS 32
#define NGRP   2
#define HDIM   128
#define O_QKV  4608
#define M_ROWS 4096

// ---------------- scratch (__device__ globals; allocation-free rule) --------
__device__ __half g_mixed[M_ROWS * O_QKV];
__device__ __half g_ctx[M_ROWS * H_DIM];
__device__ __half g_hid[M_ROWS * H_DIM];
__device__ __half g_wq[O_QKV * H_DIM];
__device__ __half g_wd[H_DIM * H_DIM];

// ---------------- helpers ----------------------------------------------------
__device__ __forceinline__ uint32_t smem_u32(const void* p) {
    uint32_t a;
    asm("{ .reg .u64 t; cvta.to.shared.u64 t, %1; cvt.u32.u64 %0, t; }" : "=r"(a) : "l"(p));
    return a;
}
__device__ __forceinline__ void cp_async16(uint32_t dst, const void* src) {
    asm volatile("cp.async.cg.shared.global [%0], [%1], 16;" :: "r"(dst), "l"(src));
}
__device__ __forceinline__ void cp_commit() {
    asm volatile("cp.async.commit_group;" ::: "memory");
}
template<int N> __device__ __forceinline__ void cp_wait() {
    asm volatile("cp.async.wait_group %0;" :: "n"(N) : "memory");
}
// D += A*B, m16n8k16 fp16 in / fp32 acc
__device__ __forceinline__ void mma16(float* d, const uint32_t* a, uint32_t b0, uint32_t b1) {
    asm volatile("mma.sync.aligned.m16n8k16.row.col.f32.f16.f16.f32 "
        "{%0,%1,%2,%3}, {%4,%5,%6,%7}, {%8,%9}, {%0,%1,%2,%3};"
        : "+f"(d[0]), "+f"(d[1]), "+f"(d[2]), "+f"(d[3])
        : "r"(a[0]), "r"(a[1]), "r"(a[2]), "r"(a[3]), "r"(b0), "r"(b1));
}
#define LDSM4(r, addr) \
    asm volatile("ldmatrix.sync.aligned.m8n8.x4.shared.b16 {%0,%1,%2,%3}, [%4];" \
        : "=r"((r)[0]), "=r"((r)[1]), "=r"((r)[2]), "=r"((r)[3]) : "r"(addr))
#define LDSM4T(r, addr) \
    asm volatile("ldmatrix.sync.aligned.m8n8.x4.trans.shared.b16 {%0,%1,%2,%3}, [%4];" \
        : "=r"((r)[0]), "=r"((r)[1]), "=r"((r)[2]), "=r"((r)[3]) : "r"(addr))

__device__ __forceinline__ uint32_t h2u(__half2 h) { return *reinterpret_cast<uint32_t*>(&h); }
__device__ __forceinline__ uint32_t packh2(float lo, float hi) {
    __half2 h = __floats2half2_rn(lo, hi);        // low 16 bits = lo
    return *reinterpret_cast<uint32_t*>(&h);
}

// ---------------- f32 -> f16 rounding pass ----------------------------------
__global__ __launch_bounds__(256) void round_f16_kernel(
    const float4* __restrict__ in, __half2* __restrict__ out, int n4)
{
    int i = blockIdx.x * blockDim.x + threadIdx.x;
    if (i >= n4) return;
    float4 v = in[i];
    out[2 * i]     = __floats2half2_rn(v.x, v.y);
    out[2 * i + 1] = __floats2half2_rn(v.z, v.w);
}

// ---------------- fp16 mma GEMM: C[M,N] = A[M,K] @ W[N,K]^T (+bias) ---------
// 512 thr (16 warps, warp grid 2Mx8N, warp tile 64x32), CTA 128x256.
// K-chunk 64 halves, 3-stage cp.async, ldmatrix for all fragments.
// smem rows padded to 72 halves (144 B).
#define A_STG_B (128 * 144)            // 18432
#define B_STG_B (256 * 144)            // 36864
#define STG_B   (A_STG_B + B_STG_B)    // 55296
#define GEMM_SMEM (3 * STG_B)          // 165888

__global__ __launch_bounds__(512, 1) void gemm_mma_kernel(
    const __half* __restrict__ A, const __half* __restrict__ W,
    const float* __restrict__ bias, void* __restrict__ Cv,
    int N, int K, int out_half)
{
    extern __shared__ char smc[];
    const uint32_t sb = smem_u32(smc);

    const int tid = threadIdx.x;
    const int wid = tid >> 5, lid = tid & 31;
    const int g = lid >> 2, c = lid & 3;
    const int m4 = lid >> 3, r8 = lid & 7;
    const int m0 = (wid & 1) * 64, n0 = (wid >> 1) * 32;
    const int row0 = blockIdx.y * 128;
    const int col0 = blockIdx.x * 256;

    // ldmatrix per-lane byte offsets
    const uint32_t laneA = ((m4 & 1) * 8 + r8) * 144 + (m4 >> 1) * 16;
    const uint32_t laneB = ((m4 >> 1) * 8 + r8) * 144 + (m4 & 1) * 16;

    float acc[4][4][4];
#pragma unroll
    for (int i = 0; i < 4; i++)
#pragma unroll
        for (int j = 0; j < 4; j++)
#pragma unroll
            for (int k = 0; k < 4; k++) acc[i][j][k] = 0.f;

    const int nchunk = K / 64;
    const int arow = tid >> 2;                 // 0..127
    const int aseg = (tid & 3) * 2;            // 0,2,4,6 (+1)
    const int brow = tid >> 1;                 // 0..255
    const int bseg = (tid & 1) * 4;            // 0 or 4 (+0..3)

#define LOADCH(ch, st) do {                                                    \
        const __half* _a = A + (size_t)(row0 + arow) * K + (ch) * 64;          \
        const __half* _b = W + (size_t)(col0 + brow) * K + (ch) * 64;          \
        uint32_t _da = sb + (st) * STG_B + arow * 144;                         \
        uint32_t _db = sb + (st) * STG_B + A_STG_B + brow * 144;               \
        cp_async16(_da + (aseg + 0) * 16, _a + (aseg + 0) * 8);                \
        cp_async16(_da + (aseg + 1) * 16, _a + (aseg + 1) * 8);                \
        cp_async16(_db + (bseg + 0) * 16, _b + (bseg + 0) * 8);                \
        cp_async16(_db + (bseg + 1) * 16, _b + (bseg + 1) * 8);                \
        cp_async16(_db + (bseg + 2) * 16, _b + (bseg + 2) * 8);                \
        cp_async16(_db + (bseg + 3) * 16, _b + (bseg + 3) * 8);                \
        cp_commit();                                                           \
    } while (0)

    LOADCH(0, 0);
    LOADCH(1, 1);

    for (int i = 0; i < nchunk; i++) {
        if (i + 1 < nchunk) cp_wait<1>(); else cp_wait<0>();
        __syncthreads();
        if (i + 2 < nchunk) LOADCH(i + 2, (i + 2) % 3);

        const uint32_t stA = sb + (i % 3) * STG_B;
        const uint32_t stB = stA + A_STG_B;
#pragma unroll
        for (int kk = 0; kk < 4; kk++) {
            uint32_t af[4][4], bf[2][4];
#pragma unroll
            for (int mt = 0; mt < 4; mt++)
                LDSM4(af[mt], stA + (m0 + mt * 16) * 144 + kk * 32 + laneA);
#pragma unroll
            for (int np = 0; np < 2; np++)
                LDSM4(bf[np], stB + (n0 + np * 16) * 144 + kk * 32 + laneB);
#pragma unroll
            for (int mt = 0; mt < 4; mt++)
#pragma unroll
                for (int np = 0; np < 2; np++) {
                    mma16(acc[mt][np * 2],     af[mt], bf[np][0], bf[np][1]);
                    mma16(acc[mt][np * 2 + 1], af[mt], bf[np][2], bf[np][3]);
                }
        }
    }
#undef LOADCH

    // epilogue
#pragma unroll
    for (int mt = 0; mt < 4; mt++) {
#pragma unroll
        for (int nt = 0; nt < 4; nt++) {
            const int rr = row0 + m0 + mt * 16 + g;
            const int cc = col0 + n0 + nt * 8 + 2 * c;
            float b0 = bias ? bias[cc] : 0.f;
            float b1 = bias ? bias[cc + 1] : 0.f;
            float v00 = acc[mt][nt][0] + b0, v01 = acc[mt][nt][1] + b1;
            float v10 = acc[mt][nt][2] + b0, v11 = acc[mt][nt][3] + b1;
            if (out_half) {
                __half* C = (__half*)Cv;
                *(__half2*)&C[(size_t)rr * N + cc]       = __floats2half2_rn(v00, v01);
                *(__half2*)&C[(size_t)(rr + 8) * N + cc] = __floats2half2_rn(v10, v11);
            } else {
                float* C = (float*)Cv;
                *(float2*)&C[(size_t)rr * N + cc]       = make_float2(v00, v01);
                *(float2*)&C[(size_t)(rr + 8) * N + cc] = make_float2(v10, v11);
            }
        }
    }
}

// ---------------- RoPE in place on g_mixed (half) ----------------------------
__global__ __launch_bounds__(256) void rope_kernel(const float* __restrict__ rope)
{
    int idx = blockIdx.x * blockDim.x + threadIdx.x;
    const int TOTAL = S_LEN * B_SZ * (NHEADS + NGRP) * 32;
    if (idx >= TOTAL) return;
    int i  = idx & 31;
    int t  = idx >> 5;
    int hh = t % (NHEADS + NGRP);
    int sb = t / (NHEADS + NGRP);
    int s  = sb >> 1;

    size_t row = (size_t)sb * O_QKV;
    int off = (hh < NHEADS) ? hh * HDIM : (NHEADS * HDIM + (hh - NHEADS) * HDIM);

    float cc = rope[s * 64 + 2 * i];
    float sn = rope[s * 64 + 2 * i + 1];
    __half2 xv = *(__half2*)&g_mixed[row + off + 2 * i];
    float x0 = __half2float(__low2half(xv));
    float x1 = __half2float(__high2half(xv));
    *(__half2*)&g_mixed[row + off + 2 * i] =
        __floats2half2_rn(x0 * cc - x1 * sn, x1 * cc + x0 * sn);
}

// ---------------- flash attention fp16, BQ=128, P-in-registers --------------
// 256 thr / 8 warps; warp w owns Q rows [w*16, w*16+16).
// K/V double-buffered via cp.async; V B-frags via ldmatrix.trans.
// smem: K0,K1,V0,V1 each 64 rows x 272 B (136-half stride) = 17408 B.
#define KB0 0
#define KB1 17408
#define VB0 34816
#define VB1 52224
#define FLASH_SMEM 69632

__global__ __launch_bounds__(256, 1) void flash_mma_kernel()
{
    extern __shared__ char smf[];
    const uint32_t sbase = smem_u32(smf);

    const int qb = blockIdx.x, h = blockIdx.y, b = blockIdx.z;
    const int grp = h >> 4;
    const int tid = threadIdx.x, wid = tid >> 5, lid = tid & 31;
    const int g = lid >> 2, c = lid & 3;
    const int m4 = lid >> 3, r8 = lid & 7;
    const int m0 = wid * 16;
    const float scale = 0.08838834764831843f;

    // ldmatrix.trans per-lane byte offset into a V buffer
    const uint32_t vlane = ((m4 & 1) * 8 + r8) * 272 + (m4 >> 1) * 16;

    // K/V tile loaders: 64 rows x 256 B = 1024 segs (4 per thread)
#define LOADK(kb, p) do {                                                       \
        _Pragma("unroll")                                                       \
        for (int _s = 0; _s < 4; _s++) {                                        \
            int _ln = tid + _s * 256;                                           \
            int _r = _ln >> 4, _c = _ln & 15;                                   \
            cp_async16(sbase + ((p) ? KB1 : KB0) + _r * 272 + _c * 16,          \
                &g_mixed[((size_t)(((kb) * 64 + _r) * 2 + b)) * O_QKV           \
                         + 4096 + grp * HDIM + _c * 8]);                        \
        } } while (0)
#define LOADV(kb, p) do {                                                       \
        _Pragma("unroll")                                                       \
        for (int _s = 0; _s < 4; _s++) {                                        \
            int _ln = tid + _s * 256;                                           \
            int _r = _ln >> 4, _c = _ln & 15;                                   \
            cp_async16(sbase + ((p) ? VB1 : VB0) + _r * 272 + _c * 16,          \
                &g_mixed[((size_t)(((kb) * 64 + _r) * 2 + b)) * O_QKV           \
                         + 4352 + grp * HDIM + _c * 8]);                        \
        } } while (0)

    // ---- stage Q (128 rows x 16 segs) through K0/V0, extract frags ----------
#pragma unroll
    for (int s = 0; s < 8; s++) {
        int ln = tid + s * 256;            // 0..2047
        int r = ln >> 4, cseg = ln & 15;
        uint32_t dst = (r < 64) ? (sbase + KB0 + r * 272 + cseg * 16)
                                : (sbase + VB0 + (r - 64) * 272 + cseg * 16);
        cp_async16(dst, &g_mixed[((size_t)((qb * 128 + r) * 2 + b)) * O_QKV
                                 + h * HDIM + cseg * 8]);
    }
    cp_commit();
    cp_wait<0>();
    __syncthreads();

    uint32_t qf[8][4];
    {
        const __half2* q2 = (const __half2*)(smf + ((wid < 4) ? KB0 : VB0));
        const int rl = (m0 & 63) + g;
#pragma unroll
        for (int kk = 0; kk < 8; kk++) {
            qf[kk][0] = h2u(q2[rl * 68 + kk * 8 + c]);
            qf[kk][1] = h2u(q2[(rl + 8) * 68 + kk * 8 + c]);
            qf[kk][2] = h2u(q2[rl * 68 + kk * 8 + c + 4]);
            qf[kk][3] = h2u(q2[(rl + 8) * 68 + kk * 8 + c + 4]);
        }
    }
    __syncthreads();   // all warps done reading before K0/V0 reload

    float o[16][4];
#pragma unroll
    for (int nt = 0; nt < 16; nt++)
#pragma unroll
        for (int j = 0; j < 4; j++) o[nt][j] = 0.f;
    float mst0 = -INFINITY, mst1 = -INFINITY, lst0 = 0.f, lst1 = 0.f;

    const int nkb = 2 * qb + 2;
    LOADK(0, 0); LOADV(0, 0); cp_commit();

    for (int kb = 0; kb < nkb; kb++) {
        const int p = kb & 1;
        cp_wait<0>();
        __syncthreads();
        if (kb + 1 < nkb) { LOADK(kb + 1, p ^ 1); LOADV(kb + 1, p ^ 1); cp_commit(); }

        const __half2* k2 = (const __half2*)(smf + (p ? KB1 : KB0));
        const uint32_t vbase = sbase + (p ? VB1 : VB0);

        // S = Q @ K^T  (16 rows x 64 cols per warp)
        float s[8][4];
#pragma unroll
        for (int nt = 0; nt < 8; nt++)
#pragma unroll
            for (int j = 0; j < 4; j++) s[nt][j] = 0.f;
#pragma unroll
        for (int kk = 0; kk < 8; kk++) {
#pragma unroll
            for (int nt = 0; nt < 8; nt++) {
                uint32_t b0 = h2u(k2[(nt * 8 + g) * 68 + kk * 8 + c]);
                uint32_t b1 = h2u(k2[(nt * 8 + g) * 68 + kk * 8 + c + 4]);
                mma16(s[nt], qf[kk], b0, b1);
            }
        }

        if (kb >= 2 * qb) {        // causal mask (diagonal region)
            const int r0 = qb * 128 + m0 + g, r1 = r0 + 8;
            const int cb = kb * 64;
#pragma unroll
            for (int nt = 0; nt < 8; nt++) {
                const int n = cb + nt * 8 + 2 * c;
                if (n > r0)     s[nt][0] = -1e30f;
                if (n + 1 > r0) s[nt][1] = -1e30f;
                if (n > r1)     s[nt][2] = -1e30f;
                if (n + 1 > r1) s[nt][3] = -1e30f;
            }
        }

        // online softmax, scale folded: p = exp((s - m) * scale)
        float rm0 = -INFINITY, rm1 = -INFINITY;
#pragma unroll
        for (int nt = 0; nt < 8; nt++) {
            rm0 = fmaxf(rm0, fmaxf(s[nt][0], s[nt][1]));
            rm1 = fmaxf(rm1, fmaxf(s[nt][2], s[nt][3]));
        }
        rm0 = fmaxf(rm0, __shfl_xor_sync(0xffffffffu, rm0, 1));
        rm0 = fmaxf(rm0, __shfl_xor_sync(0xffffffffu, rm0, 2));
        rm1 = fmaxf(rm1, __shfl_xor_sync(0xffffffffu, rm1, 1));
        rm1 = fmaxf(rm1, __shfl_xor_sync(0xffffffffu, rm1, 2));
        const float mn0 = fmaxf(mst0, rm0);
        const float mn1 = fmaxf(mst1, rm1);
        const float es0 = __expf((mst0 - mn0) * scale);
        const float es1 = __expf((mst1 - mn1) * scale);
        float rs0 = 0.f, rs1 = 0.f;
#pragma unroll
        for (int nt = 0; nt < 8; nt++) {
            s[nt][0] = __expf((s[nt][0] - mn0) * scale);
            s[nt][1] = __expf((s[nt][1] - mn0) * scale);
            s[nt][2] = __expf((s[nt][2] - mn1) * scale);
            s[nt][3] = __expf((s[nt][3] - mn1) * scale);
            rs0 += s[nt][0] + s[nt][1];
            rs1 += s[nt][2] + s[nt][3];
        }
        rs0 += __shfl_xor_sync(0xffffffffu, rs0, 1);
        rs0 += __shfl_xor_sync(0xffffffffu, rs0, 2);
        rs1 += __shfl_xor_sync(0xffffffffu, rs1, 1);
        rs1 += __shfl_xor_sync(0xffffffffu, rs1, 2);
        mst0 = mn0; mst1 = mn1;
        lst0 = lst0 * es0 + rs0;
        lst1 = lst1 * es1 + rs1;

        // O = O*escale + P @ V   (P built directly from s registers)
#pragma unroll
        for (int nt = 0; nt < 16; nt++) {
            o[nt][0] *= es0; o[nt][1] *= es0;
            o[nt][2] *= es1; o[nt][3] *= es1;
        }
#pragma unroll
        for (int kk = 0; kk < 4; kk++) {       // key-dim blocks of 16
            uint32_t a[4];
            a[0] = packh2(s[2 * kk][0],     s[2 * kk][1]);
            a[1] = packh2(s[2 * kk][2],     s[2 * kk][3]);
            a[2] = packh2(s[2 * kk + 1][0], s[2 * kk + 1][1]);
            a[3] = packh2(s[2 * kk + 1][2], s[2 * kk + 1][3]);
#pragma unroll
            for (int ntp = 0; ntp < 8; ntp++) {
                uint32_t vb[4];
                LDSM4T(vb, vbase + kk * 4352 + ntp * 32 + vlane);
                mma16(o[ntp * 2],     a, vb[0], vb[1]);
                mma16(o[ntp * 2 + 1], a, vb[2], vb[3]);
            }
        }
    }
#undef LOADK
#undef LOADV

    // normalize + write ctx (half, for the dense GEMM)
    const float inv0 = 1.f / lst0, inv1 = 1.f / lst1;
#pragma unroll
    for (int nt = 0; nt < 16; nt++) {
        const int ccol = h * HDIM + nt * 8 + 2 * c;
        size_t r0 = ((size_t)((qb * 128 + m0 + g) * 2 + b)) * H_DIM + ccol;
        size_t r1 = ((size_t)((qb * 128 + m0 + g + 8) * 2 + b)) * H_DIM + ccol;
        *(__half2*)&g_ctx[r0] = __floats2half2_rn(o[nt][0] * inv0, o[nt][1] * inv0);
        *(__half2*)&g_ctx[r1] = __floats2half2_rn(o[nt][2] * inv1, o[nt][3] * inv1);
    }
}

// ---------------------------------------------------------------------------
extern "C" void kernel_launch(void* const* d_in, const int* in_sizes, int n_in,
                              void* d_out, int out_size)
{
    const float* hidden = (const float*)d_in[0];
    const float* rope   = (const float*)d_in[2];
    const float* Wqkv   = (const float*)d_in[3];
    const float* bqkv   = (const float*)d_in[4];
    const float* Wd     = (const float*)d_in[5];
    float* out = (float*)d_out;

    __half *mixed, *ctx, *hid, *wq, *wd;
    cudaGetSymbolAddress((void**)&mixed, g_mixed);
    cudaGetSymbolAddress((void**)&ctx,   g_ctx);
    cudaGetSymbolAddress((void**)&hid,   g_hid);
    cudaGetSymbolAddress((void**)&wq,    g_wq);
    cudaGetSymbolAddress((void**)&wd,    g_wd);

    cudaFuncSetAttribute(gemm_mma_kernel,
                         cudaFuncAttributeMaxDynamicSharedMemorySize, GEMM_SMEM);
    cudaFuncSetAttribute(flash_mma_kernel,
                         cudaFuncAttributeMaxDynamicSharedMemorySize, FLASH_SMEM);

    // fp16 pre-rounding (RNE) of GEMM inputs
    {
        int n4 = M_ROWS * H_DIM / 4;
        round_f16_kernel<<<n4 / 256, 256>>>((const float4*)hidden, (__half2*)hid, n4);
    }
    {
        int n4 = O_QKV * H_DIM / 4;
        round_f16_kernel<<<n4 / 256, 256>>>((const float4*)Wqkv, (__half2*)wq, n4);
    }
    {
        int n4 = H_DIM * H_DIM / 4;
        round_f16_kernel<<<n4 / 256, 256>>>((const float4*)Wd, (__half2*)wd, n4);
    }

    // 1) QKV projection + bias (half output -> flash consumes directly)
    gemm_mma_kernel<<<dim3(O_QKV / 256, M_ROWS / 128), 512, GEMM_SMEM>>>(
        hid, wq, bqkv, mixed, O_QKV, H_DIM, 1);

    // 2) RoPE (half in/out)
    const int total = S_LEN * B_SZ * (NHEADS + NGRP) * 32;
    rope_kernel<<<(total + 255) / 256, 256>>>(rope);

    // 3) flash attention (fp16, P in registers)
    flash_mma_kernel<<<dim3(S_LEN / 128, NHEADS, B_SZ), 256, FLASH_SMEM>>>();

    // 4) dense projection (fp32 output)
    gemm_mma_kernel<<<dim3(H_DIM / 256, M_ROWS / 128), 512, GEMM_SMEM>>>(
        ctx, wd, nullptr, out, H_DIM, H_DIM, 0);
}